// round 14
// baseline (speedup 1.0000x reference)
#include <cuda_runtime.h>
#include <cuda_bf16.h>
#include <cuda_fp16.h>
#include <math.h>

// ---------------- problem constants ----------------
// B=1, N=6, X=Y=25 (L=625), W1=W2=8 (Qn=384), w1=w2=4 (Kn=96), D=128, M=4 heads, dh=32

#define LTOT 625
#define QN   384

// ---------------- device constants / scratch ----------------
__device__ __nv_bfloat16 g_wq[16384];
__device__ __nv_bfloat16 g_wk[16384];
__device__ __nv_bfloat16 g_wv[16384];
__device__ __nv_bfloat16 g_wp[16384];
__device__ __nv_bfloat16 g_tmp[(size_t)LTOT * 32 * 128];   // even-half O-mean spill
__device__ unsigned g_csb[QN * 32];                        // packed bf16x2 (cos, sin)
__device__ float g_scales[4];
__device__ float g_lnkI[256];   // interleaved (gamma, beta) fp32
__device__ float g_lnvI[256];
__device__ float g_lnqI[256];

// ---------------- helpers ----------------
__device__ __forceinline__ unsigned pk(float a, float b) {
    __nv_bfloat162 h = __floats2bfloat162_rn(a, b);
    return *reinterpret_cast<unsigned*>(&h);
}
__device__ __forceinline__ float2 bf2f(unsigned u) {
    __nv_bfloat162 h = *reinterpret_cast<__nv_bfloat162*>(&u);
    return __bfloat1622float2(h);
}
__device__ __forceinline__ __half2 u2h(unsigned u) {
    return *reinterpret_cast<__half2*>(&u);
}
__device__ __forceinline__ unsigned h2u(__half2 h) {
    return *reinterpret_cast<unsigned*>(&h);
}
// pack two f32 into f16x2: first arg -> HIGH half, second -> LOW half
__device__ __forceinline__ unsigned cvth2(float hi, float lo) {
    unsigned d;
    asm("cvt.rn.f16x2.f32 %0, %1, %2;\n" : "=r"(d) : "f"(hi), "f"(lo));
    return d;
}
__device__ __forceinline__ unsigned ex2h2(unsigned x) {
    unsigned y;
    asm("ex2.approx.f16x2 %0, %1;\n" : "=r"(y) : "r"(x));
    return y;
}
__device__ __forceinline__ unsigned ssa(const void* p) {
    return (unsigned)__cvta_generic_to_shared(p);
}
__device__ __forceinline__ void ldsm4(unsigned r[4], unsigned addr) {
    asm volatile("ldmatrix.sync.aligned.m8n8.x4.shared.b16 {%0,%1,%2,%3}, [%4];\n"
                 : "=r"(r[0]), "=r"(r[1]), "=r"(r[2]), "=r"(r[3]) : "r"(addr));
}
// bf16 mma
__device__ __forceinline__ void mma16816(float c[4], const unsigned a[4], const unsigned b[2]) {
    asm volatile(
        "mma.sync.aligned.m16n8k16.row.col.f32.bf16.bf16.f32 "
        "{%0,%1,%2,%3}, {%4,%5,%6,%7}, {%8,%9}, {%0,%1,%2,%3};\n"
        : "+f"(c[0]), "+f"(c[1]), "+f"(c[2]), "+f"(c[3])
        : "r"(a[0]), "r"(a[1]), "r"(a[2]), "r"(a[3]), "r"(b[0]), "r"(b[1]));
}
// fp16 mma (for P*V)
__device__ __forceinline__ void mma16816h(float c[4], const unsigned a[4], const unsigned b[2]) {
    asm volatile(
        "mma.sync.aligned.m16n8k16.row.col.f32.f16.f16.f32 "
        "{%0,%1,%2,%3}, {%4,%5,%6,%7}, {%8,%9}, {%0,%1,%2,%3};\n"
        : "+f"(c[0]), "+f"(c[1]), "+f"(c[2]), "+f"(c[3])
        : "r"(a[0]), "r"(a[1]), "r"(a[2]), "r"(a[3]), "r"(b[0]), "r"(b[1]));
}
__device__ __forceinline__ void cpa16(void* dst, const void* src) {
    asm volatile("cp.async.cg.shared.global [%0], [%1], 16;\n"
                 :: "r"(ssa(dst)), "l"(src));
}
__device__ __forceinline__ void cpa_commit() {
    asm volatile("cp.async.commit_group;\n");
}
template<int N> __device__ __forceinline__ void cpa_wait() {
    asm volatile("cp.async.wait_group %0;\n" :: "n"(N));
}

// ---------------- kernel 0: constants prep ----------------
__global__ __launch_bounds__(256) void prep_const_kernel(
    const float* __restrict__ wq, const float* __restrict__ wk,
    const float* __restrict__ wv, const float* __restrict__ wp,
    const float* __restrict__ freqs, const float* __restrict__ gate,
    const float* __restrict__ als,
    const float* __restrict__ lnkg, const float* __restrict__ lnkb,
    const float* __restrict__ lnvg, const float* __restrict__ lnvb,
    const float* __restrict__ lnqg, const float* __restrict__ lnqb)
{
    int idx = blockIdx.x * 256 + threadIdx.x;
    if (idx < 16384) {
        g_wq[idx] = __float2bfloat16(wq[idx]);
    } else if (idx < 32768) {
        g_wk[idx - 16384] = __float2bfloat16(wk[idx - 16384]);
    } else if (idx < 49152) {
        g_wv[idx - 32768] = __float2bfloat16(wv[idx - 32768]);
    } else if (idx < 65536) {
        g_wp[idx - 49152] = __float2bfloat16(wp[idx - 49152]);
    } else if (idx < 65536 + QN * 32) {
        int j = idx - 65536;
        float f = freqs[j];            // (400,32) row-major, t<384 prefix
        g_csb[j] = pk(cosf(f), sinf(f));
    } else if (idx < 65536 + QN * 32 + 4) {
        int m = idx - (65536 + QN * 32);
        float temp = als[m] - 0.5f * logf(32.0f);   // als + log(dh^-0.5)
        float ga = fminf(fmaxf(gate[m], 0.0f), 1.0f);
        g_scales[m] = temp * ga * 1.44269504f;      // fold log2(e): ex2 later
    } else if (idx < 65536 + QN * 32 + 4 + 768) {
        int r = idx - (65536 + QN * 32 + 4);
        int which = r >> 8, i = r & 255, c = i >> 1;
        float val;
        if (which == 0) val = (i & 1) ? lnkb[c] : lnkg[c];
        else if (which == 1) val = (i & 1) ? lnvb[c] : lnvg[c];
        else val = (i & 1) ? lnqb[c] : lnqg[c];
        if (which == 0) g_lnkI[i] = val;
        else if (which == 1) g_lnvI[i] = val;
        else g_lnqI[i] = val;
    }
}

// ---------------- smem layout (bf16 element offsets) ----------------
// sK   : 4*96*32 = 12288   K per head, SW64-XOR-swizzled (64B rows)
// sVt  : 4*32*104 = 13312  V^T[d][s] (fp16) padded stride 104, per head
// sW   : 128*128 = 16384   weights, XOR-swizzled 16B units
// raw  : 8192 elems (16 KB) fp32 LN staging 32x128; Phase C: bf16 O 64x128 swizzled
// sCS  : 2048 elems (4 KB)  packed bf16x2 (cos,sin) for current 32-row chunk
// sX   : 32*136 = 4352     LN bf16 output staging
// sLN  : 1024 elems (2 KB) two fp32 (gamma,beta)-interleaved buffers
#define E_K   0
#define E_VT  12288
#define E_W   25600
#define E_RAW 41984
#define E_CS  50176
#define E_X   52224
#define E_LN  56576
#define SMEM_ELEMS 57600
#define SMEM_BYTES (SMEM_ELEMS * 2)   // 115200 -> 2 blocks/SM

__device__ __forceinline__ void stage_w(__nv_bfloat16* sW, const __nv_bfloat16* w, int tid) {
    #pragma unroll
    for (int u = tid; u < 2048; u += 256) {
        int row = u >> 4, cu = u & 15;
        cpa16(sW + row * 128 + ((cu ^ (row & 7)) << 3), w + u * 8);
    }
}
__device__ __forceinline__ void stage_chunk(float* raw, const float* x, int l,
                                            int t0, int sh, int msk, int tid) {
    #pragma unroll
    for (int j = 0; j < 4; j++) {
        int idx = tid + 256 * j;
        int row = idx >> 5, c4 = idx & 31;
        int t = t0 + row;
        int n = t >> sh, rem = t & msk;
        cpa16(raw + row * 128 + c4 * 4,
              x + ((size_t)(n * LTOT + l) * (msk + 1) + rem) * 128 + c4 * 4);
    }
}
__device__ __forceinline__ void stage_cs(unsigned* sCS, const unsigned* src, int tid) {
    cpa16(sCS + tid * 4, src + tid * 4);   // 256 threads x 16B = 4 KB
}

// ---------------- fused kernel: one block per l-tile, 2 blocks/SM ----------------
__global__ __launch_bounds__(256, 2) void fused_kernel(
    const float* __restrict__ q, const float* __restrict__ k,
    const float* __restrict__ v, const float* __restrict__ skip,
    const float* __restrict__ bq, const float* __restrict__ bk,
    const float* __restrict__ bv, const float* __restrict__ bproj,
    float* __restrict__ out)
{
    extern __shared__ __nv_bfloat16 sm[];
    __nv_bfloat16* sK  = sm + E_K;
    __nv_bfloat16* sVt = sm + E_VT;
    __nv_bfloat16* sW  = sm + E_W;
    float* raw = reinterpret_cast<float*>(sm + E_RAW);
    __nv_bfloat16* rawO = sm + E_RAW;
    unsigned* sCS = reinterpret_cast<unsigned*>(sm + E_CS);
    __nv_bfloat16* sX  = sm + E_X;
    float* sLN0 = reinterpret_cast<float*>(sm + E_LN);        // 256 floats
    float* sLN1 = sLN0 + 256;
    __half* sVtH = reinterpret_cast<__half*>(sVt);

    int l = blockIdx.x;
    int tid = threadIdx.x;
    int wid = tid >> 5, lane = tid & 31, gq = lane >> 2, t4 = lane & 3;
    int mrow = (wid & 1) * 16;            // 16-row half within 32-row chunk
    int mh = wid >> 1;                    // head
    int lrow = tid >> 3, lsub = tid & 7;  // LN: 8 threads/row, 32 rows

    unsigned sWb = ssa(sW);
    unsigned abase = ssa(&sX[(mrow + (lane & 15)) * 136 + ((lane >> 4) << 3)]);
    int wu0 = (lane >> 3) & 1;

    // weight B-fragment lane constants (swizzled sW; 16B units, row stride 256 B)
    int o01 = mh * 32 + ((lane >> 4) << 3) + (lane & 7);
    unsigned wrow01 = sWb + o01 * 256;
    unsigned wrow23 = wrow01 + 4096;      // +16 output rows
    int wrx = o01 & 7;

    // K fragment bases (SW64-swizzled sK): second kk block = addr ^ 32
    char* sKb = reinterpret_cast<char*>(sK) + mh * 6144;
    unsigned kb0[6];
    {
        unsigned sKhb = ssa(sKb);
        #pragma unroll
        for (int p = 0; p < 6; p++) {
            int tr = (2 * p + (lane >> 4)) * 8 + (lane & 7);
            kb0[p] = sKhb + tr * 64 + ((wu0 ^ ((tr >> 1) & 3)) << 4);
        }
    }
    // V^T fragment bases (padded stride 104)
    __nv_bfloat16* sVh = sVt + mh * 32 * 104;
    unsigned vb[2];
    #pragma unroll
    for (int p = 0; p < 2; p++)
        vb[p] = ssa(&sVh[((2 * p + (lane >> 4)) * 8 + (lane & 7)) * 104 + (((lane >> 3) & 1) << 3)]);
    float sc = g_scales[mh];

    // initial staging: wk + LN params (K->sLN0, V->sLN1) + first k chunk
    stage_w(sW, g_wk, tid);
    if (tid < 64) cpa16(sLN0 + tid * 4, g_lnkI + tid * 4);
    else if (tid < 128) cpa16(sLN1 + (tid - 64) * 4, g_lnvI + (tid - 64) * 4);
    cpa_commit();
    stage_chunk(raw, k, l, 0, 4, 15, tid);
    cpa_commit();

    // =========================== Phase A: K (i=0..2) then V (i=3..5) prep ===========================
    for (int i = 0; i < 6; i++) {
        int isV = (i >= 3);
        cpa_wait<0>();
        __syncthreads();                        // chunk i arrived; prev epilogue reads of sCS done
        if (i < 3) { stage_cs(sCS, g_csb + i * 1024, tid); cpa_commit(); }     // [A]
        if (i == 3) { stage_w(sW, g_wv, tid); cpa_commit(); }                  // [W]

        // LayerNorm 32 rows (E[x^2] identity, interleaved trees, params from smem)
        {
            const float* lnp = isV ? sLN1 : sLN0;
            const float* rp = raw + lrow * 128;
            float vv[16];
            #pragma unroll
            for (int i4 = 0; i4 < 4; i4++) {
                float4 f = *reinterpret_cast<const float4*>(rp + (lsub + 8 * i4) * 4);
                vv[4 * i4] = f.x; vv[4 * i4 + 1] = f.y; vv[4 * i4 + 2] = f.z; vv[4 * i4 + 3] = f.w;
            }
            float s = 0.f, s2 = 0.f;
            #pragma unroll
            for (int i2 = 0; i2 < 16; i2++) { s += vv[i2]; s2 = fmaf(vv[i2], vv[i2], s2); }
            #pragma unroll
            for (int o = 1; o < 8; o <<= 1) {
                s += __shfl_xor_sync(0xffffffffu, s, o);
                s2 += __shfl_xor_sync(0xffffffffu, s2, o);
            }
            float mu = s * (1.0f / 128.0f);
            float rs = rsqrtf(fmaf(-mu, mu, s2 * (1.0f / 128.0f)) + 1e-5f);
            unsigned* xw = reinterpret_cast<unsigned*>(sX) + lrow * 68;
            #pragma unroll
            for (int i4 = 0; i4 < 4; i4++) {
                float4 gb0 = *reinterpret_cast<const float4*>(lnp + lsub * 8 + i4 * 64);
                float4 gb1 = *reinterpret_cast<const float4*>(lnp + lsub * 8 + i4 * 64 + 4);
                float a0 = (vv[4 * i4]     - mu) * rs * gb0.x + gb0.y;
                float a1 = (vv[4 * i4 + 1] - mu) * rs * gb0.z + gb0.w;
                float a2 = (vv[4 * i4 + 2] - mu) * rs * gb1.x + gb1.y;
                float a3 = (vv[4 * i4 + 3] - mu) * rs * gb1.z + gb1.w;
                xw[2 * lsub + 16 * i4]     = pk(a0, a1);
                xw[2 * lsub + 16 * i4 + 1] = pk(a2, a3);
            }
        }
        __syncthreads();                        // raw free, sX ready
        if (i == 3) cpa_wait<0>();              // wv must be resident before GEMM
        if (i < 2)       stage_chunk(raw, k, l, (i + 1) * 32, 4, 15, tid);
        else if (i < 5)  stage_chunk(raw, v, l, (i - 2) * 32, 4, 15, tid);
        else             stage_chunk(raw, q, l, 0, 6, 63, tid);
        cpa_commit();

        // GEMM: 32 rows x 128 cols
        float acc[4][4] = {};
        #pragma unroll
        for (int kk = 0; kk < 128; kk += 16) {
            unsigned uoff = ((((kk >> 3) + wu0) ^ wrx) << 4);
            unsigned a[4], b01[4], b23[4];
            ldsm4(a, abase + kk * 2);
            ldsm4(b01, wrow01 + uoff);
            ldsm4(b23, wrow23 + uoff);
            mma16816(acc[0], a, &b01[0]);
            mma16816(acc[1], a, &b01[2]);
            mma16816(acc[2], a, &b23[0]);
            mma16816(acc[3], a, &b23[2]);
        }
        cpa_wait<1>();                          // cs chunk arrived (no-op for V iters)

        if (!isV) {
            // K: +bias -> RoPE(bf16 trig from sCS) -> sK (SW64 swizzled)
            #pragma unroll
            for (int r = 0; r < 2; r++) {
                int lt = mrow + gq + 8 * r;
                int t = i * 32 + lt;
                #pragma unroll
                for (int ntl = 0; ntl < 2; ntl++) {
                    int jlo = ntl * 8 + 2 * t4;
                    int jhi = jlo + 16;
                    float2 blo = *reinterpret_cast<const float2*>(&bk[mh * 32 + jlo]);
                    float2 bhi = *reinterpret_cast<const float2*>(&bk[mh * 32 + jhi]);
                    float plo0 = acc[ntl][2 * r] + blo.x;
                    float plo1 = acc[ntl][2 * r + 1] + blo.y;
                    float phi0 = acc[ntl + 2][2 * r] + bhi.x;
                    float phi1 = acc[ntl + 2][2 * r + 1] + bhi.y;
                    uint2 ulo = *reinterpret_cast<const uint2*>(&sCS[lt * 32 + jlo]);
                    uint2 uhi = *reinterpret_cast<const uint2*>(&sCS[lt * 32 + jhi]);
                    float2 cs0 = bf2f(ulo.x), cs1 = bf2f(ulo.y);
                    float2 cs2 = bf2f(uhi.x), cs3 = bf2f(uhi.y);
                    unsigned off0 = t * 64 + jlo * 2;
                    unsigned off1 = t * 64 + jhi * 2;
                    *reinterpret_cast<unsigned*>(sKb + (off0 ^ ((off0 >> 3) & 0x30))) =
                        pk(plo0 * cs0.x - phi0 * cs0.y, plo1 * cs1.x - phi1 * cs1.y);
                    *reinterpret_cast<unsigned*>(sKb + (off1 ^ ((off1 >> 3) & 0x30))) =
                        pk(phi0 * cs2.x + plo0 * cs2.y, phi1 * cs3.x + plo1 * cs3.y);
                }
            }
        } else {
            // V: +bias -> transpose into sVt as FP16 (for fp16 PV mma)
            #pragma unroll
            for (int r = 0; r < 2; r++) {
                int t = (i - 3) * 32 + mrow + gq + 8 * r;
                #pragma unroll
                for (int ntl = 0; ntl < 2; ntl++) {
                    int jlo = ntl * 8 + 2 * t4;
                    int jhi = jlo + 16;
                    float2 blo = *reinterpret_cast<const float2*>(&bv[mh * 32 + jlo]);
                    float2 bhi = *reinterpret_cast<const float2*>(&bv[mh * 32 + jhi]);
                    sVtH[(mh * 32 + jlo) * 104 + t]     = __float2half(acc[ntl][2 * r] + blo.x);
                    sVtH[(mh * 32 + jlo + 1) * 104 + t] = __float2half(acc[ntl][2 * r + 1] + blo.y);
                    sVtH[(mh * 32 + jhi) * 104 + t]     = __float2half(acc[ntl + 2][2 * r] + bhi.x);
                    sVtH[(mh * 32 + jhi + 1) * 104 + t] = __float2half(acc[ntl + 2][2 * r + 1] + bhi.y);
                }
            }
        }
    }

    // ---- A->B transition: wq + Q LN params into place ----
    __syncthreads();                       // last GEMM's sW reads + sVt writes complete
    stage_w(sW, g_wq, tid);
    if (tid < 64) cpa16(sLN0 + tid * 4, g_lnqI + tid * 4);
    cpa_commit();
    cpa_wait<0>();                         // wq + q chunk0 resident
    __syncthreads();

    // =========================== Phase B: Q prep + attention + mean ===========================
    float moacc[4][4] = {};

    for (int j = 0; j < 12; j++) {
        int qc = (j < 6) ? 2 * j : 2 * j - 11;   // even uv-half first, then odd
        cpa_wait<0>();
        __syncthreads();                          // raw_j arrived; prev sCS reads done
        stage_cs(sCS, g_csb + qc * 1024, tid); cpa_commit();

        // LayerNorm (q): E[x^2] identity, params from smem
        {
            const float* rp = raw + lrow * 128;
            float vv[16];
            #pragma unroll
            for (int i4 = 0; i4 < 4; i4++) {
                float4 f = *reinterpret_cast<const float4*>(rp + (lsub + 8 * i4) * 4);
                vv[4 * i4] = f.x; vv[4 * i4 + 1] = f.y; vv[4 * i4 + 2] = f.z; vv[4 * i4 + 3] = f.w;
            }
            float s = 0.f, s2 = 0.f;
            #pragma unroll
            for (int i2 = 0; i2 < 16; i2++) { s += vv[i2]; s2 = fmaf(vv[i2], vv[i2], s2); }
            #pragma unroll
            for (int o = 1; o < 8; o <<= 1) {
                s += __shfl_xor_sync(0xffffffffu, s, o);
                s2 += __shfl_xor_sync(0xffffffffu, s2, o);
            }
            float mu = s * (1.0f / 128.0f);
            float rs = rsqrtf(fmaf(-mu, mu, s2 * (1.0f / 128.0f)) + 1e-5f);
            unsigned* xw = reinterpret_cast<unsigned*>(sX) + lrow * 68;
            #pragma unroll
            for (int i4 = 0; i4 < 4; i4++) {
                float4 gb0 = *reinterpret_cast<const float4*>(sLN0 + lsub * 8 + i4 * 64);
                float4 gb1 = *reinterpret_cast<const float4*>(sLN0 + lsub * 8 + i4 * 64 + 4);
                float a0 = (vv[4 * i4]     - mu) * rs * gb0.x + gb0.y;
                float a1 = (vv[4 * i4 + 1] - mu) * rs * gb0.z + gb0.w;
                float a2 = (vv[4 * i4 + 2] - mu) * rs * gb1.x + gb1.y;
                float a3 = (vv[4 * i4 + 3] - mu) * rs * gb1.z + gb1.w;
                xw[2 * lsub + 16 * i4]     = pk(a0, a1);
                xw[2 * lsub + 16 * i4 + 1] = pk(a2, a3);
            }
        }
        __syncthreads();
        if (j < 11) {
            int j2 = j + 1;
            int qc2 = (j2 < 6) ? 2 * j2 : 2 * j2 - 11;
            stage_chunk(raw, q, l, qc2 * 32, 6, 63, tid);
            cpa_commit();
        }

        // q GEMM
        float acc[4][4] = {};
        #pragma unroll
        for (int kk = 0; kk < 128; kk += 16) {
            unsigned uoff = ((((kk >> 3) + wu0) ^ wrx) << 4);
            unsigned a[4], b01[4], b23[4];
            ldsm4(a, abase + kk * 2);
            ldsm4(b01, wrow01 + uoff);
            ldsm4(b23, wrow23 + uoff);
            mma16816(acc[0], a, &b01[0]);
            mma16816(acc[1], a, &b01[2]);
            mma16816(acc[2], a, &b23[0]);
            mma16816(acc[3], a, &b23[2]);
        }
        if (j < 11) cpa_wait<1>(); else cpa_wait<0>();   // cs arrived

        // epilogue: +bias -> RoPE(bf16 trig) -> *scale(log2e folded) -> A fragments
        unsigned aq0[4], aq1[4];
        {
            float F[4][4];
            #pragma unroll
            for (int r = 0; r < 2; r++) {
                int lt = mrow + gq + 8 * r;
                #pragma unroll
                for (int ntl = 0; ntl < 2; ntl++) {
                    int jlo = ntl * 8 + 2 * t4;
                    int jhi = jlo + 16;
                    float2 blo = *reinterpret_cast<const float2*>(&bq[mh * 32 + jlo]);
                    float2 bhi = *reinterpret_cast<const float2*>(&bq[mh * 32 + jhi]);
                    float plo0 = acc[ntl][2 * r] + blo.x;
                    float plo1 = acc[ntl][2 * r + 1] + blo.y;
                    float phi0 = acc[ntl + 2][2 * r] + bhi.x;
                    float phi1 = acc[ntl + 2][2 * r + 1] + bhi.y;
                    uint2 ulo = *reinterpret_cast<const uint2*>(&sCS[lt * 32 + jlo]);
                    uint2 uhi = *reinterpret_cast<const uint2*>(&sCS[lt * 32 + jhi]);
                    float2 cs0 = bf2f(ulo.x), cs1 = bf2f(ulo.y);
                    float2 cs2 = bf2f(uhi.x), cs3 = bf2f(uhi.y);
                    F[ntl][2 * r]         = (plo0 * cs0.x - phi0 * cs0.y) * sc;
                    F[ntl][2 * r + 1]     = (plo1 * cs1.x - phi1 * cs1.y) * sc;
                    F[ntl + 2][2 * r]     = (phi0 * cs2.x + plo0 * cs2.y) * sc;
                    F[ntl + 2][2 * r + 1] = (phi1 * cs3.x + plo1 * cs3.y) * sc;
                }
            }
            aq0[0] = pk(F[0][0], F[0][1]); aq0[1] = pk(F[0][2], F[0][3]);
            aq0[2] = pk(F[1][0], F[1][1]); aq0[3] = pk(F[1][2], F[1][3]);
            aq1[0] = pk(F[2][0], F[2][1]); aq1[1] = pk(F[2][2], F[2][3]);
            aq1[2] = pk(F[3][0], F[3][1]); aq1[3] = pk(F[3][2], F[3][3]);
        }

        // S = Q K^T over 96 keys (SW64-swizzled K; kk block 1 = addr ^ 32)
        float sacc[12][4] = {};
        #pragma unroll
        for (int p = 0; p < 6; p++) {
            unsigned b[4];
            ldsm4(b, kb0[p]);
            mma16816(sacc[2 * p], aq0, &b[0]);
            mma16816(sacc[2 * p + 1], aq0, &b[2]);
        }
        #pragma unroll
        for (int p = 0; p < 6; p++) {
            unsigned b[4];
            ldsm4(b, kb0[p] ^ 32u);
            mma16816(sacc[2 * p], aq1, &b[0]);
            mma16816(sacc[2 * p + 1], aq1, &b[2]);
        }

        // fp16x2 softmax
        unsigned hx[12], hy[12];
        #pragma unroll
        for (int nt = 0; nt < 12; nt++) {
            hx[nt] = ex2h2(cvth2(sacc[nt][1], sacc[nt][0]));
            hy[nt] = ex2h2(cvth2(sacc[nt][3], sacc[nt][2]));
        }
        __half2 s2x = u2h(hx[0]), s2y = u2h(hy[0]);
        #pragma unroll
        for (int nt = 1; nt < 12; nt++) {
            s2x = __hadd2(s2x, u2h(hx[nt]));
            s2y = __hadd2(s2y, u2h(hy[nt]));
        }
        float sm0 = __low2float(s2x) + __high2float(s2x);
        float sm1 = __low2float(s2y) + __high2float(s2y);
        sm0 += __shfl_xor_sync(0xffffffffu, sm0, 1);
        sm0 += __shfl_xor_sync(0xffffffffu, sm0, 2);
        sm1 += __shfl_xor_sync(0xffffffffu, sm1, 1);
        sm1 += __shfl_xor_sync(0xffffffffu, sm1, 2);
        float r0i = __fdividef(0.16666667f, sm0);
        float r1i = __fdividef(0.16666667f, sm1);
        unsigned rr0 = cvth2(r0i, r0i);
        unsigned rr1 = cvth2(r1i, r1i);
        #pragma unroll
        for (int nt = 0; nt < 12; nt++) {
            hx[nt] = h2u(__hmul2(u2h(hx[nt]), u2h(rr0)));
            hy[nt] = h2u(__hmul2(u2h(hy[nt]), u2h(rr1)));
        }

        // O += (P/6) V via fp16 mma — hx/hy ARE the A fragments
        #pragma unroll
        for (int c6 = 0; c6 < 6; c6++) {
            unsigned a[4];
            a[0] = hx[2 * c6];
            a[1] = hy[2 * c6];
            a[2] = hx[2 * c6 + 1];
            a[3] = hy[2 * c6 + 1];
            #pragma unroll
            for (int p = 0; p < 2; p++) {
                unsigned b[4];
                ldsm4(b, vb[p] + c6 * 32);
                mma16816h(moacc[2 * p], a, &b[0]);
                mma16816h(moacc[2 * p + 1], a, &b[2]);
            }
        }

        if (j == 5) {
            // flush even uv-half mean to global scratch; reset accumulator
            #pragma unroll
            for (int nt = 0; nt < 4; nt++) {
                int col = mh * 32 + nt * 8 + 2 * t4;
                #pragma unroll
                for (int r = 0; r < 2; r++) {
                    int uv = mrow + gq + 8 * r;
                    *reinterpret_cast<unsigned*>(g_tmp + (size_t)l * 4096 + uv * 128 + col) =
                        pk(moacc[nt][2 * r], moacc[nt][2 * r + 1]);
                }
            }
            #pragma unroll
            for (int nt = 0; nt < 4; nt++)
                #pragma unroll
                for (int e = 0; e < 4; e++) moacc[nt][e] = 0.f;
        }
    }

    // =========================== Phase C: mean -> proj -> +skip -> out ===========================
    __syncthreads();   // all attention reads of sK/sVt/sW/raw done

    // odd uv-half: registers -> rawO rows 32..63 (swizzled bf16 64x128)
    #pragma unroll
    for (int nt = 0; nt < 4; nt++) {
        int col = mh * 32 + nt * 8 + 2 * t4;
        int cu = col >> 3;
        #pragma unroll
        for (int r = 0; r < 2; r++) {
            int row = 32 + mrow + gq + 8 * r;
            *reinterpret_cast<unsigned*>(&rawO[row * 128 + ((cu ^ (row & 7)) << 3) + (col & 7)]) =
                pk(moacc[nt][2 * r], moacc[nt][2 * r + 1]);
        }
    }
    // stage wp, even uv-half (g_tmp), skip
    stage_w(sW, g_wp, tid);
    #pragma unroll
    for (int u = tid; u < 512; u += 256) {
        int row = u >> 4, cu = u & 15;
        cpa16(&rawO[row * 128 + ((cu ^ (row & 7)) << 3)],
              g_tmp + (size_t)l * 4096 + row * 128 + cu * 8);
    }
    float* sSkip = reinterpret_cast<float*>(sm + E_K);   // 32 KB inside dead sK/sVt region
    #pragma unroll
    for (int u = tid; u < 2048; u += 256)
        cpa16(sSkip + u * 4, skip + (size_t)l * 8192 + u * 4);
    cpa_commit();
    cpa_wait<0>();
    __syncthreads();

    // proj GEMM: 64 rows x 128 cols
    {
        int rh = wid & 3, cg = wid >> 2;
        int prowA = rh * 16 + (lane & 15);
        unsigned paRow = ssa(rawO) + prowA * 256;
        int parx = prowA & 7, pau0 = lane >> 4;
        int op = cg * 64 + ((lane >> 4) << 3) + (lane & 7);
        unsigned pw0 = sWb + op * 256;
        int prx = op & 7;
        float pacc[8][4] = {};
        #pragma unroll
        for (int kk = 0; kk < 128; kk += 16) {
            unsigned a[4];
            ldsm4(a, paRow + ((((kk >> 3) + pau0) ^ parx) << 4));
            unsigned uoff = ((((kk >> 3) + wu0) ^ prx) << 4);
            #pragma unroll
            for (int p = 0; p < 4; p++) {
                unsigned b[4];
                ldsm4(b, pw0 + p * 4096 + uoff);
                mma16816(pacc[2 * p], a, &b[0]);
                mma16816(pacc[2 * p + 1], a, &b[2]);
            }
        }
        #pragma unroll
        for (int nt = 0; nt < 8; nt++) {
            int col = cg * 64 + nt * 8 + 2 * t4;
            float2 bp = *reinterpret_cast<const float2*>(&bproj[col]);
            #pragma unroll
            for (int r = 0; r < 2; r++) {
                int rloc = rh * 16 + gq + 8 * r;
                float2 sk = *reinterpret_cast<const float2*>(sSkip + rloc * 128 + col);
                float2 o2;
                o2.x = pacc[nt][2 * r] + bp.x + sk.x;
                o2.y = pacc[nt][2 * r + 1] + bp.y + sk.y;
                *reinterpret_cast<float2*>(out + ((size_t)l * 64 + rloc) * 128 + col) = o2;
            }
        }
    }
}

// ---------------- launch ----------------
extern "C" void kernel_launch(void* const* d_in, const int* in_sizes, int n_in,
                              void* d_out, int out_size) {
    const float* q     = (const float*)d_in[0];
    const float* k     = (const float*)d_in[1];
    const float* v     = (const float*)d_in[2];
    const float* skip  = (const float*)d_in[3];
    const float* freqs = (const float*)d_in[4];
    const float* gate  = (const float*)d_in[5];
    const float* lnqg  = (const float*)d_in[6];
    const float* lnqb  = (const float*)d_in[7];
    const float* lnkg  = (const float*)d_in[8];
    const float* lnkb  = (const float*)d_in[9];
    const float* lnvg  = (const float*)d_in[10];
    const float* lnvb  = (const float*)d_in[11];
    const float* wq    = (const float*)d_in[12];
    const float* bq    = (const float*)d_in[13];
    const float* wk    = (const float*)d_in[14];
    const float* bk    = (const float*)d_in[15];
    const float* wv    = (const float*)d_in[16];
    const float* bv    = (const float*)d_in[17];
    const float* wproj = (const float*)d_in[18];
    const float* bproj = (const float*)d_in[19];
    const float* als   = (const float*)d_in[20];
    float* out = (float*)d_out;

    static int smem_set = 0;
    if (!smem_set) {
        cudaFuncSetAttribute(fused_kernel, cudaFuncAttributeMaxDynamicSharedMemorySize, SMEM_BYTES);
        smem_set = 1;
    }

    prep_const_kernel<<<308, 256>>>(wq, wk, wv, wproj, freqs, gate, als,
                                    lnkg, lnkb, lnvg, lnvb, lnqg, lnqb);
    fused_kernel<<<LTOT, 256, SMEM_BYTES>>>(q, k, v, skip,
                                            bq, bk, bv, bproj, out);
}

// round 15
// speedup vs baseline: 1.0284x; 1.0284x over previous
#include <cuda_runtime.h>
#include <cuda_bf16.h>
#include <cuda_fp16.h>
#include <math.h>

// ---------------- problem constants ----------------
// B=1, N=6, X=Y=25 (L=625), W1=W2=8 (Qn=384), w1=w2=4 (Kn=96), D=128, M=4 heads, dh=32

#define LTOT 625
#define QN   384

// ---------------- device constants / scratch ----------------
__device__ __nv_bfloat16 g_wq[16384];
__device__ __nv_bfloat16 g_wk[16384];
__device__ __nv_bfloat16 g_wv[16384];
__device__ __nv_bfloat16 g_wp[16384];
__device__ __nv_bfloat16 g_tmp[(size_t)LTOT * 32 * 128];   // even-half O-mean spill
__device__ unsigned g_csb[QN * 32];                        // packed bf16x2 (cos, sin)
__device__ float g_scales[4];

// ---------------- helpers ----------------
__device__ __forceinline__ unsigned pk(float a, float b) {
    __nv_bfloat162 h = __floats2bfloat162_rn(a, b);
    return *reinterpret_cast<unsigned*>(&h);
}
__device__ __forceinline__ float2 bf2f(unsigned u) {
    __nv_bfloat162 h = *reinterpret_cast<__nv_bfloat162*>(&u);
    return __bfloat1622float2(h);
}
__device__ __forceinline__ __half2 u2h(unsigned u) {
    return *reinterpret_cast<__half2*>(&u);
}
__device__ __forceinline__ unsigned h2u(__half2 h) {
    return *reinterpret_cast<unsigned*>(&h);
}
// pack two f32 into f16x2: first arg -> HIGH half, second -> LOW half
__device__ __forceinline__ unsigned cvth2(float hi, float lo) {
    unsigned d;
    asm("cvt.rn.f16x2.f32 %0, %1, %2;\n" : "=r"(d) : "f"(hi), "f"(lo));
    return d;
}
// fp16 pack with (lo, hi) argument order matching pk()
__device__ __forceinline__ unsigned pkh(float lo, float hi) {
    return cvth2(hi, lo);
}
__device__ __forceinline__ unsigned ex2h2(unsigned x) {
    unsigned y;
    asm("ex2.approx.f16x2 %0, %1;\n" : "=r"(y) : "r"(x));
    return y;
}
__device__ __forceinline__ unsigned ssa(const void* p) {
    return (unsigned)__cvta_generic_to_shared(p);
}
__device__ __forceinline__ void ldsm4(unsigned r[4], unsigned addr) {
    asm volatile("ldmatrix.sync.aligned.m8n8.x4.shared.b16 {%0,%1,%2,%3}, [%4];\n"
                 : "=r"(r[0]), "=r"(r[1]), "=r"(r[2]), "=r"(r[3]) : "r"(addr));
}
// bf16 mma, fp32 accum
__device__ __forceinline__ void mma16816(float c[4], const unsigned a[4], const unsigned b[2]) {
    asm volatile(
        "mma.sync.aligned.m16n8k16.row.col.f32.bf16.bf16.f32 "
        "{%0,%1,%2,%3}, {%4,%5,%6,%7}, {%8,%9}, {%0,%1,%2,%3};\n"
        : "+f"(c[0]), "+f"(c[1]), "+f"(c[2]), "+f"(c[3])
        : "r"(a[0]), "r"(a[1]), "r"(a[2]), "r"(a[3]), "r"(b[0]), "r"(b[1]));
}
// fp16 mma, fp32 accum (for P*V)
__device__ __forceinline__ void mma16816h(float c[4], const unsigned a[4], const unsigned b[2]) {
    asm volatile(
        "mma.sync.aligned.m16n8k16.row.col.f32.f16.f16.f32 "
        "{%0,%1,%2,%3}, {%4,%5,%6,%7}, {%8,%9}, {%0,%1,%2,%3};\n"
        : "+f"(c[0]), "+f"(c[1]), "+f"(c[2]), "+f"(c[3])
        : "r"(a[0]), "r"(a[1]), "r"(a[2]), "r"(a[3]), "r"(b[0]), "r"(b[1]));
}
// fp16 mma, fp16 accum (for S = QK^T): D = 2 packed f16x2 regs, layout == softmax pair format
__device__ __forceinline__ void mma16816hh(unsigned c[2], const unsigned a[4], const unsigned b[2]) {
    asm volatile(
        "mma.sync.aligned.m16n8k16.row.col.f16.f16.f16.f16 "
        "{%0,%1}, {%2,%3,%4,%5}, {%6,%7}, {%0,%1};\n"
        : "+r"(c[0]), "+r"(c[1])
        : "r"(a[0]), "r"(a[1]), "r"(a[2]), "r"(a[3]), "r"(b[0]), "r"(b[1]));
}
__device__ __forceinline__ void cpa16(void* dst, const void* src) {
    asm volatile("cp.async.cg.shared.global [%0], [%1], 16;\n"
                 :: "r"(ssa(dst)), "l"(src));
}
__device__ __forceinline__ void cpa_commit() {
    asm volatile("cp.async.commit_group;\n");
}
template<int N> __device__ __forceinline__ void cpa_wait() {
    asm volatile("cp.async.wait_group %0;\n" :: "n"(N));
}

// ---------------- kernel 0: constants prep ----------------
__global__ __launch_bounds__(256) void prep_const_kernel(
    const float* __restrict__ wq, const float* __restrict__ wk,
    const float* __restrict__ wv, const float* __restrict__ wp,
    const float* __restrict__ freqs, const float* __restrict__ gate,
    const float* __restrict__ als)
{
    int idx = blockIdx.x * 256 + threadIdx.x;
    if (idx < 16384) {
        g_wq[idx] = __float2bfloat16(wq[idx]);
    } else if (idx < 32768) {
        g_wk[idx - 16384] = __float2bfloat16(wk[idx - 16384]);
    } else if (idx < 49152) {
        g_wv[idx - 32768] = __float2bfloat16(wv[idx - 32768]);
    } else if (idx < 65536) {
        g_wp[idx - 49152] = __float2bfloat16(wp[idx - 49152]);
    } else if (idx < 65536 + QN * 32) {
        int j = idx - 65536;
        float f = freqs[j];            // (400,32) row-major, t<384 prefix
        g_csb[j] = pk(cosf(f), sinf(f));
    } else if (idx < 65536 + QN * 32 + 4) {
        int m = idx - (65536 + QN * 32);
        float temp = als[m] - 0.5f * logf(32.0f);   // als + log(dh^-0.5)
        float ga = fminf(fmaxf(gate[m], 0.0f), 1.0f);
        g_scales[m] = temp * ga * 1.44269504f;      // fold log2(e): ex2 later
    }
}

// ---------------- smem layout (bf16 element offsets) ----------------
// sK   : 4*96*32 = 12288   K per head (FP16!), SW64-XOR-swizzled (64B rows)
// sVt  : 4*32*104 = 13312  V^T[d][s] (fp16) padded stride 104, per head
// sW   : 128*128 = 16384   weights, XOR-swizzled 16B units
// raw  : 8192 elems (16 KB) fp32 LN staging 32x128; Phase C: bf16 O 64x128 swizzled
// sCS  : 2048 elems (4 KB)  packed bf16x2 (cos,sin) for current 32-row chunk
// sX   : 32*136 = 4352     LN bf16 output staging
#define E_K   0
#define E_VT  12288
#define E_W   25600
#define E_RAW 41984
#define E_CS  50176
#define E_X   52224
#define SMEM_ELEMS 56576
#define SMEM_BYTES (SMEM_ELEMS * 2)   // 113152 -> 2 blocks/SM

__device__ __forceinline__ void stage_w(__nv_bfloat16* sW, const __nv_bfloat16* w, int tid) {
    #pragma unroll
    for (int u = tid; u < 2048; u += 256) {
        int row = u >> 4, cu = u & 15;
        cpa16(sW + row * 128 + ((cu ^ (row & 7)) << 3), w + u * 8);
    }
}
__device__ __forceinline__ void stage_chunk(float* raw, const float* x, int l,
                                            int t0, int sh, int msk, int tid) {
    #pragma unroll
    for (int j = 0; j < 4; j++) {
        int idx = tid + 256 * j;
        int row = idx >> 5, c4 = idx & 31;
        int t = t0 + row;
        int n = t >> sh, rem = t & msk;
        cpa16(raw + row * 128 + c4 * 4,
              x + ((size_t)(n * LTOT + l) * (msk + 1) + rem) * 128 + c4 * 4);
    }
}
__device__ __forceinline__ void stage_cs(unsigned* sCS, const unsigned* src, int tid) {
    cpa16(sCS + tid * 4, src + tid * 4);   // 256 threads x 16B = 4 KB
}

// ---------------- fused kernel: one block per l-tile, 2 blocks/SM ----------------
__global__ __launch_bounds__(256, 2) void fused_kernel(
    const float* __restrict__ q, const float* __restrict__ k,
    const float* __restrict__ v, const float* __restrict__ skip,
    const float* __restrict__ lnqg, const float* __restrict__ lnqb,
    const float* __restrict__ lnkg, const float* __restrict__ lnkb,
    const float* __restrict__ lnvg, const float* __restrict__ lnvb,
    const float* __restrict__ bq, const float* __restrict__ bk,
    const float* __restrict__ bv, const float* __restrict__ bproj,
    float* __restrict__ out)
{
    extern __shared__ __nv_bfloat16 sm[];
    __nv_bfloat16* sK  = sm + E_K;
    __nv_bfloat16* sVt = sm + E_VT;
    __nv_bfloat16* sW  = sm + E_W;
    float* raw = reinterpret_cast<float*>(sm + E_RAW);
    __nv_bfloat16* rawO = sm + E_RAW;
    unsigned* sCS = reinterpret_cast<unsigned*>(sm + E_CS);
    __nv_bfloat16* sX  = sm + E_X;
    __half* sVtH = reinterpret_cast<__half*>(sVt);

    int l = blockIdx.x;
    int tid = threadIdx.x;
    int wid = tid >> 5, lane = tid & 31, gq = lane >> 2, t4 = lane & 3;
    int mrow = (wid & 1) * 16;            // 16-row half within 32-row chunk
    int mh = wid >> 1;                    // head
    int lrow = tid >> 3, lsub = tid & 7;  // LN: 8 threads/row

    unsigned sWb = ssa(sW);
    unsigned abase = ssa(&sX[(mrow + (lane & 15)) * 136 + ((lane >> 4) << 3)]);

    // weight B-fragment lane constants (swizzled sW; 16B units, row stride 256 B)
    int o01 = mh * 32 + ((lane >> 4) << 3) + (lane & 7);
    unsigned wrow01 = sWb + o01 * 256;
    unsigned wrow23 = wrow01 + 4096;      // +16 output rows
    int wrx = o01 & 7;
    int wu0 = (lane >> 3) & 1;

    // K fragment bases (SW64-swizzled sK): second kk block = addr ^ 32
    char* sKb = reinterpret_cast<char*>(sK) + mh * 6144;
    unsigned kb0[6];
    {
        unsigned sKhb = ssa(sKb);
        int u0 = (lane >> 3) & 1;
        #pragma unroll
        for (int p = 0; p < 6; p++) {
            int tr = (2 * p + (lane >> 4)) * 8 + (lane & 7);
            kb0[p] = sKhb + tr * 64 + ((u0 ^ ((tr >> 1) & 3)) << 4);
        }
    }
    // V^T fragment bases (padded stride 104)
    __nv_bfloat16* sVh = sVt + mh * 32 * 104;
    unsigned vb[2];
    #pragma unroll
    for (int p = 0; p < 2; p++)
        vb[p] = ssa(&sVh[((2 * p + (lane >> 4)) * 8 + (lane & 7)) * 104 + (((lane >> 3) & 1) << 3)]);
    float sc = g_scales[mh];

    // initial: wk + first k chunk
    stage_w(sW, g_wk, tid);
    cpa_commit();
    stage_chunk(raw, k, l, 0, 4, 15, tid);
    cpa_commit();

    // =========================== Phase A: K (i=0..2) then V (i=3..5) prep ===========================
    for (int i = 0; i < 6; i++) {
        int isV = (i >= 3);
        cpa_wait<0>();
        __syncthreads();                        // chunk i arrived; prev epilogue reads of sCS done
        if (i < 3) { stage_cs(sCS, g_csb + i * 1024, tid); cpa_commit(); }     // [A]
        if (i == 3) { stage_w(sW, g_wv, tid); cpa_commit(); }                  // [W]

        // LayerNorm 32 rows
        {
            const float* lng  = isV ? lnvg : lnkg;
            const float* lnb_ = isV ? lnvb : lnkb;
            const float* rp = raw + lrow * 128;
            float vv[16];
            #pragma unroll
            for (int i4 = 0; i4 < 4; i4++) {
                float4 f = *reinterpret_cast<const float4*>(rp + (lsub + 8 * i4) * 4);
                vv[4 * i4] = f.x; vv[4 * i4 + 1] = f.y; vv[4 * i4 + 2] = f.z; vv[4 * i4 + 3] = f.w;
            }
            float s = 0.f;
            #pragma unroll
            for (int i2 = 0; i2 < 16; i2++) s += vv[i2];
            #pragma unroll
            for (int o = 1; o < 8; o <<= 1) s += __shfl_xor_sync(0xffffffffu, s, o);
            float mu = s * (1.0f / 128.0f);
            float q2 = 0.f;
            #pragma unroll
            for (int i2 = 0; i2 < 16; i2++) { float d = vv[i2] - mu; q2 += d * d; }
            #pragma unroll
            for (int o = 1; o < 8; o <<= 1) q2 += __shfl_xor_sync(0xffffffffu, q2, o);
            float rs = rsqrtf(q2 * (1.0f / 128.0f) + 1e-5f);
            unsigned* xw = reinterpret_cast<unsigned*>(sX) + lrow * 68;
            #pragma unroll
            for (int i4 = 0; i4 < 4; i4++) {
                int c0 = lsub * 4 + i4 * 32;
                float a0 = (vv[4 * i4]     - mu) * rs * lng[c0]     + lnb_[c0];
                float a1 = (vv[4 * i4 + 1] - mu) * rs * lng[c0 + 1] + lnb_[c0 + 1];
                float a2 = (vv[4 * i4 + 2] - mu) * rs * lng[c0 + 2] + lnb_[c0 + 2];
                float a3 = (vv[4 * i4 + 3] - mu) * rs * lng[c0 + 3] + lnb_[c0 + 3];
                xw[2 * lsub + 16 * i4]     = pk(a0, a1);
                xw[2 * lsub + 16 * i4 + 1] = pk(a2, a3);
            }
        }
        __syncthreads();                        // raw free, sX ready
        if (i == 3) cpa_wait<0>();              // wv must be resident before GEMM
        // prefetch next chunk into raw
        if (i < 2)       stage_chunk(raw, k, l, (i + 1) * 32, 4, 15, tid);
        else if (i < 5)  stage_chunk(raw, v, l, (i - 2) * 32, 4, 15, tid);
        else             stage_chunk(raw, q, l, 0, 6, 63, tid);
        cpa_commit();

        // GEMM: 32 rows x 128 cols
        float acc[4][4] = {};
        #pragma unroll
        for (int kk = 0; kk < 128; kk += 16) {
            unsigned uoff = ((((kk >> 3) + wu0) ^ wrx) << 4);
            unsigned a[4], b01[4], b23[4];
            ldsm4(a, abase + kk * 2);
            ldsm4(b01, wrow01 + uoff);
            ldsm4(b23, wrow23 + uoff);
            mma16816(acc[0], a, &b01[0]);
            mma16816(acc[1], a, &b01[2]);
            mma16816(acc[2], a, &b23[0]);
            mma16816(acc[3], a, &b23[2]);
        }
        cpa_wait<1>();                          // cs chunk arrived (no-op for V iters)

        if (!isV) {
            // K: +bias -> RoPE(bf16 trig from sCS) -> sK as FP16 (SW64 swizzled)
            #pragma unroll
            for (int r = 0; r < 2; r++) {
                int lt = mrow + gq + 8 * r;
                int t = i * 32 + lt;
                #pragma unroll
                for (int ntl = 0; ntl < 2; ntl++) {
                    int jlo = ntl * 8 + 2 * t4;
                    int jhi = jlo + 16;
                    float2 blo = *reinterpret_cast<const float2*>(&bk[mh * 32 + jlo]);
                    float2 bhi = *reinterpret_cast<const float2*>(&bk[mh * 32 + jhi]);
                    float plo0 = acc[ntl][2 * r] + blo.x;
                    float plo1 = acc[ntl][2 * r + 1] + blo.y;
                    float phi0 = acc[ntl + 2][2 * r] + bhi.x;
                    float phi1 = acc[ntl + 2][2 * r + 1] + bhi.y;
                    uint2 ulo = *reinterpret_cast<const uint2*>(&sCS[lt * 32 + jlo]);
                    uint2 uhi = *reinterpret_cast<const uint2*>(&sCS[lt * 32 + jhi]);
                    float2 cs0 = bf2f(ulo.x), cs1 = bf2f(ulo.y);
                    float2 cs2 = bf2f(uhi.x), cs3 = bf2f(uhi.y);
                    unsigned off0 = t * 64 + jlo * 2;
                    unsigned off1 = t * 64 + jhi * 2;
                    *reinterpret_cast<unsigned*>(sKb + (off0 ^ ((off0 >> 3) & 0x30))) =
                        pkh(plo0 * cs0.x - phi0 * cs0.y, plo1 * cs1.x - phi1 * cs1.y);
                    *reinterpret_cast<unsigned*>(sKb + (off1 ^ ((off1 >> 3) & 0x30))) =
                        pkh(phi0 * cs2.x + plo0 * cs2.y, phi1 * cs3.x + plo1 * cs3.y);
                }
            }
        } else {
            // V: +bias -> transpose into sVt as FP16 (for fp16 PV mma)
            #pragma unroll
            for (int r = 0; r < 2; r++) {
                int t = (i - 3) * 32 + mrow + gq + 8 * r;
                #pragma unroll
                for (int ntl = 0; ntl < 2; ntl++) {
                    int jlo = ntl * 8 + 2 * t4;
                    int jhi = jlo + 16;
                    float2 blo = *reinterpret_cast<const float2*>(&bv[mh * 32 + jlo]);
                    float2 bhi = *reinterpret_cast<const float2*>(&bv[mh * 32 + jhi]);
                    sVtH[(mh * 32 + jlo) * 104 + t]     = __float2half(acc[ntl][2 * r] + blo.x);
                    sVtH[(mh * 32 + jlo + 1) * 104 + t] = __float2half(acc[ntl][2 * r + 1] + blo.y);
                    sVtH[(mh * 32 + jhi) * 104 + t]     = __float2half(acc[ntl + 2][2 * r] + bhi.x);
                    sVtH[(mh * 32 + jhi + 1) * 104 + t] = __float2half(acc[ntl + 2][2 * r + 1] + bhi.y);
                }
            }
        }
    }

    // =========================== Phase B: Q prep + attention + mean ===========================
    float moacc[4][4] = {};

    for (int j = 0; j < 12; j++) {
        int qc = (j < 6) ? 2 * j : 2 * j - 11;   // even uv-half first, then odd
        cpa_wait<0>();
        __syncthreads();                          // raw_j arrived; prev sCS reads done
        stage_cs(sCS, g_csb + qc * 1024, tid); cpa_commit();
        if (j == 0) { stage_w(sW, g_wq, tid); cpa_commit(); }

        // LayerNorm (q)
        {
            const float* rp = raw + lrow * 128;
            float vv[16];
            #pragma unroll
            for (int i4 = 0; i4 < 4; i4++) {
                float4 f = *reinterpret_cast<const float4*>(rp + (lsub + 8 * i4) * 4);
                vv[4 * i4] = f.x; vv[4 * i4 + 1] = f.y; vv[4 * i4 + 2] = f.z; vv[4 * i4 + 3] = f.w;
            }
            float s = 0.f;
            #pragma unroll
            for (int i2 = 0; i2 < 16; i2++) s += vv[i2];
            #pragma unroll
            for (int o = 1; o < 8; o <<= 1) s += __shfl_xor_sync(0xffffffffu, s, o);
            float mu = s * (1.0f / 128.0f);
            float q2 = 0.f;
            #pragma unroll
            for (int i2 = 0; i2 < 16; i2++) { float d = vv[i2] - mu; q2 += d * d; }
            #pragma unroll
            for (int o = 1; o < 8; o <<= 1) q2 += __shfl_xor_sync(0xffffffffu, q2, o);
            float rs = rsqrtf(q2 * (1.0f / 128.0f) + 1e-5f);
            unsigned* xw = reinterpret_cast<unsigned*>(sX) + lrow * 68;
            #pragma unroll
            for (int i4 = 0; i4 < 4; i4++) {
                int c0 = lsub * 4 + i4 * 32;
                float a0 = (vv[4 * i4]     - mu) * rs * lnqg[c0]     + lnqb[c0];
                float a1 = (vv[4 * i4 + 1] - mu) * rs * lnqg[c0 + 1] + lnqb[c0 + 1];
                float a2 = (vv[4 * i4 + 2] - mu) * rs * lnqg[c0 + 2] + lnqb[c0 + 2];
                float a3 = (vv[4 * i4 + 3] - mu) * rs * lnqg[c0 + 3] + lnqb[c0 + 3];
                xw[2 * lsub + 16 * i4]     = pk(a0, a1);
                xw[2 * lsub + 16 * i4 + 1] = pk(a2, a3);
            }
        }
        __syncthreads();
        if (j == 0) cpa_wait<0>();              // wq resident before GEMM
        if (j < 11) {
            int j2 = j + 1;
            int qc2 = (j2 < 6) ? 2 * j2 : 2 * j2 - 11;
            stage_chunk(raw, q, l, qc2 * 32, 6, 63, tid);
            cpa_commit();
        }

        // q GEMM
        float acc[4][4] = {};
        #pragma unroll
        for (int kk = 0; kk < 128; kk += 16) {
            unsigned uoff = ((((kk >> 3) + wu0) ^ wrx) << 4);
            unsigned a[4], b01[4], b23[4];
            ldsm4(a, abase + kk * 2);
            ldsm4(b01, wrow01 + uoff);
            ldsm4(b23, wrow23 + uoff);
            mma16816(acc[0], a, &b01[0]);
            mma16816(acc[1], a, &b01[2]);
            mma16816(acc[2], a, &b23[0]);
            mma16816(acc[3], a, &b23[2]);
        }
        if (j < 11) cpa_wait<1>(); else cpa_wait<0>();   // cs arrived

        // epilogue: +bias -> RoPE(bf16 trig) -> *scale(log2e folded) -> FP16 A fragments
        unsigned aq0[4], aq1[4];
        {
            float F[4][4];
            #pragma unroll
            for (int r = 0; r < 2; r++) {
                int lt = mrow + gq + 8 * r;
                #pragma unroll
                for (int ntl = 0; ntl < 2; ntl++) {
                    int jlo = ntl * 8 + 2 * t4;
                    int jhi = jlo + 16;
                    float2 blo = *reinterpret_cast<const float2*>(&bq[mh * 32 + jlo]);
                    float2 bhi = *reinterpret_cast<const float2*>(&bq[mh * 32 + jhi]);
                    float plo0 = acc[ntl][2 * r] + blo.x;
                    float plo1 = acc[ntl][2 * r + 1] + blo.y;
                    float phi0 = acc[ntl + 2][2 * r] + bhi.x;
                    float phi1 = acc[ntl + 2][2 * r + 1] + bhi.y;
                    uint2 ulo = *reinterpret_cast<const uint2*>(&sCS[lt * 32 + jlo]);
                    uint2 uhi = *reinterpret_cast<const uint2*>(&sCS[lt * 32 + jhi]);
                    float2 cs0 = bf2f(ulo.x), cs1 = bf2f(ulo.y);
                    float2 cs2 = bf2f(uhi.x), cs3 = bf2f(uhi.y);
                    F[ntl][2 * r]         = (plo0 * cs0.x - phi0 * cs0.y) * sc;
                    F[ntl][2 * r + 1]     = (plo1 * cs1.x - phi1 * cs1.y) * sc;
                    F[ntl + 2][2 * r]     = (phi0 * cs2.x + plo0 * cs2.y) * sc;
                    F[ntl + 2][2 * r + 1] = (phi1 * cs3.x + plo1 * cs3.y) * sc;
                }
            }
            aq0[0] = pkh(F[0][0], F[0][1]); aq0[1] = pkh(F[0][2], F[0][3]);
            aq0[2] = pkh(F[1][0], F[1][1]); aq0[3] = pkh(F[1][2], F[1][3]);
            aq1[0] = pkh(F[2][0], F[2][1]); aq1[1] = pkh(F[2][2], F[2][3]);
            aq1[2] = pkh(F[3][0], F[3][1]); aq1[3] = pkh(F[3][2], F[3][3]);
        }

        // S = Q K^T over 96 keys (fp16 accumulators; D pairs == softmax pair layout)
        unsigned sacc2[12][2] = {};
        #pragma unroll
        for (int p = 0; p < 6; p++) {
            unsigned b[4];
            ldsm4(b, kb0[p]);
            mma16816hh(sacc2[2 * p], aq0, &b[0]);
            mma16816hh(sacc2[2 * p + 1], aq0, &b[2]);
        }
        #pragma unroll
        for (int p = 0; p < 6; p++) {
            unsigned b[4];
            ldsm4(b, kb0[p] ^ 32u);
            mma16816hh(sacc2[2 * p], aq1, &b[0]);
            mma16816hh(sacc2[2 * p + 1], aq1, &b[2]);
        }

        // fp16x2 softmax directly on mma outputs
        unsigned hx[12], hy[12];
        #pragma unroll
        for (int nt = 0; nt < 12; nt++) {
            hx[nt] = ex2h2(sacc2[nt][0]);
            hy[nt] = ex2h2(sacc2[nt][1]);
        }
        __half2 s2x = u2h(hx[0]), s2y = u2h(hy[0]);
        #pragma unroll
        for (int nt = 1; nt < 12; nt++) {
            s2x = __hadd2(s2x, u2h(hx[nt]));
            s2y = __hadd2(s2y, u2h(hy[nt]));
        }
        float sm0 = __low2float(s2x) + __high2float(s2x);
        float sm1 = __low2float(s2y) + __high2float(s2y);
        sm0 += __shfl_xor_sync(0xffffffffu, sm0, 1);
        sm0 += __shfl_xor_sync(0xffffffffu, sm0, 2);
        sm1 += __shfl_xor_sync(0xffffffffu, sm1, 1);
        sm1 += __shfl_xor_sync(0xffffffffu, sm1, 2);
        float r0i = __fdividef(0.16666667f, sm0);
        float r1i = __fdividef(0.16666667f, sm1);
        unsigned rr0 = cvth2(r0i, r0i);
        unsigned rr1 = cvth2(r1i, r1i);
        #pragma unroll
        for (int nt = 0; nt < 12; nt++) {
            hx[nt] = h2u(__hmul2(u2h(hx[nt]), u2h(rr0)));
            hy[nt] = h2u(__hmul2(u2h(hy[nt]), u2h(rr1)));
        }

        // O += (P/6) V via fp16 mma — hx/hy ARE the A fragments
        #pragma unroll
        for (int c6 = 0; c6 < 6; c6++) {
            unsigned a[4];
            a[0] = hx[2 * c6];
            a[1] = hy[2 * c6];
            a[2] = hx[2 * c6 + 1];
            a[3] = hy[2 * c6 + 1];
            #pragma unroll
            for (int p = 0; p < 2; p++) {
                unsigned b[4];
                ldsm4(b, vb[p] + c6 * 32);
                mma16816h(moacc[2 * p], a, &b[0]);
                mma16816h(moacc[2 * p + 1], a, &b[2]);
            }
        }

        if (j == 5) {
            // flush even uv-half mean to global scratch; reset accumulator
            #pragma unroll
            for (int nt = 0; nt < 4; nt++) {
                int col = mh * 32 + nt * 8 + 2 * t4;
                #pragma unroll
                for (int r = 0; r < 2; r++) {
                    int uv = mrow + gq + 8 * r;
                    *reinterpret_cast<unsigned*>(g_tmp + (size_t)l * 4096 + uv * 128 + col) =
                        pk(moacc[nt][2 * r], moacc[nt][2 * r + 1]);
                }
            }
            #pragma unroll
            for (int nt = 0; nt < 4; nt++)
                #pragma unroll
                for (int e = 0; e < 4; e++) moacc[nt][e] = 0.f;
        }
    }

    // =========================== Phase C: mean -> proj -> +skip -> out ===========================
    __syncthreads();   // all attention reads of sK/sVt/sW/raw done

    // odd uv-half: registers -> rawO rows 32..63 (swizzled bf16 64x128)
    #pragma unroll
    for (int nt = 0; nt < 4; nt++) {
        int col = mh * 32 + nt * 8 + 2 * t4;
        int cu = col >> 3;
        #pragma unroll
        for (int r = 0; r < 2; r++) {
            int row = 32 + mrow + gq + 8 * r;
            *reinterpret_cast<unsigned*>(&rawO[row * 128 + ((cu ^ (row & 7)) << 3) + (col & 7)]) =
                pk(moacc[nt][2 * r], moacc[nt][2 * r + 1]);
        }
    }
    // stage wp, even uv-half (g_tmp), skip
    stage_w(sW, g_wp, tid);
    #pragma unroll
    for (int u = tid; u < 512; u += 256) {
        int row = u >> 4, cu = u & 15;
        cpa16(&rawO[row * 128 + ((cu ^ (row & 7)) << 3)],
              g_tmp + (size_t)l * 4096 + row * 128 + cu * 8);
    }
    float* sSkip = reinterpret_cast<float*>(sm + E_K);   // 32 KB inside dead sK/sVt region
    #pragma unroll
    for (int u = tid; u < 2048; u += 256)
        cpa16(sSkip + u * 4, skip + (size_t)l * 8192 + u * 4);
    cpa_commit();
    cpa_wait<0>();
    __syncthreads();

    // proj GEMM: 64 rows x 128 cols
    {
        int rh = wid & 3, cg = wid >> 2;
        int prowA = rh * 16 + (lane & 15);
        unsigned paRow = ssa(rawO) + prowA * 256;
        int parx = prowA & 7, pau0 = lane >> 4;
        int op = cg * 64 + ((lane >> 4) << 3) + (lane & 7);
        unsigned pw0 = sWb + op * 256;
        int prx = op & 7;
        float pacc[8][4] = {};
        #pragma unroll
        for (int kk = 0; kk < 128; kk += 16) {
            unsigned a[4];
            ldsm4(a, paRow + ((((kk >> 3) + pau0) ^ parx) << 4));
            unsigned uoff = ((((kk >> 3) + wu0) ^ prx) << 4);
            #pragma unroll
            for (int p = 0; p < 4; p++) {
                unsigned b[4];
                ldsm4(b, pw0 + p * 4096 + uoff);
                mma16816(pacc[2 * p], a, &b[0]);
                mma16816(pacc[2 * p + 1], a, &b[2]);
            }
        }
        #pragma unroll
        for (int nt = 0; nt < 8; nt++) {
            int col = cg * 64 + nt * 8 + 2 * t4;
            float2 bp = *reinterpret_cast<const float2*>(&bproj[col]);
            #pragma unroll
            for (int r = 0; r < 2; r++) {
                int rloc = rh * 16 + gq + 8 * r;
                float2 sk = *reinterpret_cast<const float2*>(sSkip + rloc * 128 + col);
                float2 o2;
                o2.x = pacc[nt][2 * r] + bp.x + sk.x;
                o2.y = pacc[nt][2 * r + 1] + bp.y + sk.y;
                *reinterpret_cast<float2*>(out + ((size_t)l * 64 + rloc) * 128 + col) = o2;
            }
        }
    }
}

// ---------------- launch ----------------
extern "C" void kernel_launch(void* const* d_in, const int* in_sizes, int n_in,
                              void* d_out, int out_size) {
    const float* q     = (const float*)d_in[0];
    const float* k     = (const float*)d_in[1];
    const float* v     = (const float*)d_in[2];
    const float* skip  = (const float*)d_in[3];
    const float* freqs = (const float*)d_in[4];
    const float* gate  = (const float*)d_in[5];
    const float* lnqg  = (const float*)d_in[6];
    const float* lnqb  = (const float*)d_in[7];
    const float* lnkg  = (const float*)d_in[8];
    const float* lnkb  = (const float*)d_in[9];
    const float* lnvg  = (const float*)d_in[10];
    const float* lnvb  = (const float*)d_in[11];
    const float* wq    = (const float*)d_in[12];
    const float* bq    = (const float*)d_in[13];
    const float* wk    = (const float*)d_in[14];
    const float* bk    = (const float*)d_in[15];
    const float* wv    = (const float*)d_in[16];
    const float* bv    = (const float*)d_in[17];
    const float* wproj = (const float*)d_in[18];
    const float* bproj = (const float*)d_in[19];
    const float* als   = (const float*)d_in[20];
    float* out = (float*)d_out;

    static int smem_set = 0;
    if (!smem_set) {
        cudaFuncSetAttribute(fused_kernel, cudaFuncAttributeMaxDynamicSharedMemorySize, SMEM_BYTES);
        smem_set = 1;
    }

    prep_const_kernel<<<305, 256>>>(wq, wk, wv, wproj, freqs, gate, als);
    fused_kernel<<<LTOT, 256, SMEM_BYTES>>>(q, k, v, skip,
                                            lnqg, lnqb, lnkg, lnkb, lnvg, lnvb,
                                            bq, bk, bv, bproj, out);
}

// round 16
// speedup vs baseline: 1.0570x; 1.0278x over previous
#include <cuda_runtime.h>
#include <cuda_bf16.h>
#include <cuda_fp16.h>
#include <math.h>

// ---------------- problem constants ----------------
// B=1, N=6, X=Y=25 (L=625), W1=W2=8 (Qn=384), w1=w2=4 (Kn=96), D=128, M=4 heads, dh=32

#define LTOT 625
#define QN   384

// ---------------- device constants / scratch ----------------
__device__ __nv_bfloat16 g_wq[16384];
__device__ __nv_bfloat16 g_wk[16384];
__device__ __nv_bfloat16 g_wv[16384];
__device__ __nv_bfloat16 g_wp[16384];
__device__ __nv_bfloat16 g_tmp[(size_t)LTOT * 32 * 128];   // even-half O-mean spill
__device__ unsigned g_csb[QN * 32];                        // packed bf16x2 (cos, sin)
__device__ float g_scales[4];

// ---------------- helpers ----------------
__device__ __forceinline__ unsigned pk(float a, float b) {
    __nv_bfloat162 h = __floats2bfloat162_rn(a, b);
    return *reinterpret_cast<unsigned*>(&h);
}
__device__ __forceinline__ float2 bf2f(unsigned u) {
    __nv_bfloat162 h = *reinterpret_cast<__nv_bfloat162*>(&u);
    return __bfloat1622float2(h);
}
__device__ __forceinline__ __half2 u2h(unsigned u) {
    return *reinterpret_cast<__half2*>(&u);
}
__device__ __forceinline__ unsigned h2u(__half2 h) {
    return *reinterpret_cast<unsigned*>(&h);
}
// pack two f32 into f16x2: first arg -> HIGH half, second -> LOW half
__device__ __forceinline__ unsigned cvth2(float hi, float lo) {
    unsigned d;
    asm("cvt.rn.f16x2.f32 %0, %1, %2;\n" : "=r"(d) : "f"(hi), "f"(lo));
    return d;
}
// fp16 pack with (lo, hi) argument order matching pk()
__device__ __forceinline__ unsigned pkh(float lo, float hi) {
    return cvth2(hi, lo);
}
__device__ __forceinline__ unsigned ex2h2(unsigned x) {
    unsigned y;
    asm("ex2.approx.f16x2 %0, %1;\n" : "=r"(y) : "r"(x));
    return y;
}
__device__ __forceinline__ unsigned ssa(const void* p) {
    return (unsigned)__cvta_generic_to_shared(p);
}
__device__ __forceinline__ void ldsm4(unsigned r[4], unsigned addr) {
    asm volatile("ldmatrix.sync.aligned.m8n8.x4.shared.b16 {%0,%1,%2,%3}, [%4];\n"
                 : "=r"(r[0]), "=r"(r[1]), "=r"(r[2]), "=r"(r[3]) : "r"(addr));
}
// bf16 mma, fp32 accum
__device__ __forceinline__ void mma16816(float c[4], const unsigned a[4], const unsigned b[2]) {
    asm volatile(
        "mma.sync.aligned.m16n8k16.row.col.f32.bf16.bf16.f32 "
        "{%0,%1,%2,%3}, {%4,%5,%6,%7}, {%8,%9}, {%0,%1,%2,%3};\n"
        : "+f"(c[0]), "+f"(c[1]), "+f"(c[2]), "+f"(c[3])
        : "r"(a[0]), "r"(a[1]), "r"(a[2]), "r"(a[3]), "r"(b[0]), "r"(b[1]));
}
// fp16 mma, fp32 accum (for P*V)
__device__ __forceinline__ void mma16816h(float c[4], const unsigned a[4], const unsigned b[2]) {
    asm volatile(
        "mma.sync.aligned.m16n8k16.row.col.f32.f16.f16.f32 "
        "{%0,%1,%2,%3}, {%4,%5,%6,%7}, {%8,%9}, {%0,%1,%2,%3};\n"
        : "+f"(c[0]), "+f"(c[1]), "+f"(c[2]), "+f"(c[3])
        : "r"(a[0]), "r"(a[1]), "r"(a[2]), "r"(a[3]), "r"(b[0]), "r"(b[1]));
}
// fp16 mma, fp16 accum (for S = QK^T): D = 2 packed f16x2 regs, layout == softmax pair format
__device__ __forceinline__ void mma16816hh(unsigned c[2], const unsigned a[4], const unsigned b[2]) {
    asm volatile(
        "mma.sync.aligned.m16n8k16.row.col.f16.f16.f16.f16 "
        "{%0,%1}, {%2,%3,%4,%5}, {%6,%7}, {%0,%1};\n"
        : "+r"(c[0]), "+r"(c[1])
        : "r"(a[0]), "r"(a[1]), "r"(a[2]), "r"(a[3]), "r"(b[0]), "r"(b[1]));
}
__device__ __forceinline__ void cpa16(void* dst, const void* src) {
    asm volatile("cp.async.cg.shared.global [%0], [%1], 16;\n"
                 :: "r"(ssa(dst)), "l"(src));
}
__device__ __forceinline__ void cpa_commit() {
    asm volatile("cp.async.commit_group;\n");
}
template<int N> __device__ __forceinline__ void cpa_wait() {
    asm volatile("cp.async.wait_group %0;\n" :: "n"(N));
}

// ---------------- kernel 0: constants prep ----------------
__global__ __launch_bounds__(256) void prep_const_kernel(
    const float* __restrict__ wq, const float* __restrict__ wk,
    const float* __restrict__ wv, const float* __restrict__ wp,
    const float* __restrict__ freqs, const float* __restrict__ gate,
    const float* __restrict__ als)
{
    int idx = blockIdx.x * 256 + threadIdx.x;
    if (idx < 16384) {
        g_wq[idx] = __float2bfloat16(wq[idx]);
    } else if (idx < 32768) {
        g_wk[idx - 16384] = __float2bfloat16(wk[idx - 16384]);
    } else if (idx < 49152) {
        g_wv[idx - 32768] = __float2bfloat16(wv[idx - 32768]);
    } else if (idx < 65536) {
        g_wp[idx - 49152] = __float2bfloat16(wp[idx - 49152]);
    } else if (idx < 65536 + QN * 32) {
        int j = idx - 65536;
        float f = freqs[j];            // (400,32) row-major, t<384 prefix
        g_csb[j] = pk(cosf(f), sinf(f));
    } else if (idx < 65536 + QN * 32 + 4) {
        int m = idx - (65536 + QN * 32);
        float temp = als[m] - 0.5f * logf(32.0f);   // als + log(dh^-0.5)
        float ga = fminf(fmaxf(gate[m], 0.0f), 1.0f);
        g_scales[m] = temp * ga * 1.44269504f;      // fold log2(e): ex2 later
    }
}

// ---------------- smem layout (bf16 element offsets) ----------------
// sK   : 4*96*32 = 12288   K per head (FP16), SW64-XOR-swizzled (64B rows)
// sVt  : 4*32*104 = 13312  V^T[d][s] (fp16) padded stride 104, per head
// sW   : 128*128 = 16384   weights, XOR-swizzled 16B units
// raw  : 8192 elems (16 KB) fp32 LN staging 32x128; Phase C: bf16 O 64x128 swizzled
// sCS  : 2048 elems (4 KB)  packed bf16x2 (cos,sin) for current 32-row chunk
// sX   : 32*136 = 4352     LN bf16 output staging
#define E_K   0
#define E_VT  12288
#define E_W   25600
#define E_RAW 41984
#define E_CS  50176
#define E_X   52224
#define SMEM_ELEMS 56576
#define SMEM_BYTES (SMEM_ELEMS * 2)   // 113152 -> 2 blocks/SM

__device__ __forceinline__ void stage_w(__nv_bfloat16* sW, const __nv_bfloat16* w, int tid) {
    #pragma unroll
    for (int u = tid; u < 2048; u += 256) {
        int row = u >> 4, cu = u & 15;
        cpa16(sW + row * 128 + ((cu ^ (row & 7)) << 3), w + u * 8);
    }
}
__device__ __forceinline__ void stage_chunk(float* raw, const float* x, int l,
                                            int t0, int sh, int msk, int tid) {
    #pragma unroll
    for (int j = 0; j < 4; j++) {
        int idx = tid + 256 * j;
        int row = idx >> 5, c4 = idx & 31;
        int t = t0 + row;
        int n = t >> sh, rem = t & msk;
        cpa16(raw + row * 128 + c4 * 4,
              x + ((size_t)(n * LTOT + l) * (msk + 1) + rem) * 128 + c4 * 4);
    }
}
__device__ __forceinline__ void stage_cs(unsigned* sCS, const unsigned* src, int tid) {
    cpa16(sCS + tid * 4, src + tid * 4);   // 256 threads x 16B = 4 KB
}

// ---------------- fused kernel: one block per l-tile, 2 blocks/SM ----------------
__global__ __launch_bounds__(256, 2) void fused_kernel(
    const float* __restrict__ q, const float* __restrict__ k,
    const float* __restrict__ v, const float* __restrict__ skip,
    const float* __restrict__ lnqg, const float* __restrict__ lnqb,
    const float* __restrict__ lnkg, const float* __restrict__ lnkb,
    const float* __restrict__ lnvg, const float* __restrict__ lnvb,
    const float* __restrict__ bq, const float* __restrict__ bk,
    const float* __restrict__ bv, const float* __restrict__ bproj,
    float* __restrict__ out)
{
    extern __shared__ __nv_bfloat16 sm[];
    __nv_bfloat16* sK  = sm + E_K;
    __nv_bfloat16* sVt = sm + E_VT;
    __nv_bfloat16* sW  = sm + E_W;
    float* raw = reinterpret_cast<float*>(sm + E_RAW);
    __nv_bfloat16* rawO = sm + E_RAW;
    unsigned* sCS = reinterpret_cast<unsigned*>(sm + E_CS);
    __nv_bfloat16* sX  = sm + E_X;
    __half* sVtH = reinterpret_cast<__half*>(sVt);

    int l = blockIdx.x;
    int tid = threadIdx.x;
    int wid = tid >> 5, lane = tid & 31, gq = lane >> 2, t4 = lane & 3;
    int mrow = (wid & 1) * 16;            // 16-row half within 32-row chunk
    int mh = wid >> 1;                    // head
    int lrow = tid >> 3, lsub = tid & 7;  // LN: 8 threads/row

    unsigned sWb = ssa(sW);
    unsigned abase = ssa(&sX[(mrow + (lane & 15)) * 136 + ((lane >> 4) << 3)]);

    // weight B-fragment lane constants (swizzled sW; 16B units, row stride 256 B)
    int o01 = mh * 32 + ((lane >> 4) << 3) + (lane & 7);
    unsigned wrow01 = sWb + o01 * 256;
    unsigned wrow23 = wrow01 + 4096;      // +16 output rows
    int wrx = o01 & 7;
    int wu0 = (lane >> 3) & 1;

    // K fragment bases (SW64-swizzled sK): second kk block = addr ^ 32
    char* sKb = reinterpret_cast<char*>(sK) + mh * 6144;
    unsigned kb0[6];
    {
        unsigned sKhb = ssa(sKb);
        int u0 = (lane >> 3) & 1;
        #pragma unroll
        for (int p = 0; p < 6; p++) {
            int tr = (2 * p + (lane >> 4)) * 8 + (lane & 7);
            kb0[p] = sKhb + tr * 64 + ((u0 ^ ((tr >> 1) & 3)) << 4);
        }
    }
    // V^T fragment bases (padded stride 104)
    __nv_bfloat16* sVh = sVt + mh * 32 * 104;
    unsigned vb[2];
    #pragma unroll
    for (int p = 0; p < 2; p++)
        vb[p] = ssa(&sVh[((2 * p + (lane >> 4)) * 8 + (lane & 7)) * 104 + (((lane >> 3) & 1) << 3)]);
    float sc = g_scales[mh];

    // initial: wk + first k chunk
    stage_w(sW, g_wk, tid);
    cpa_commit();
    stage_chunk(raw, k, l, 0, 4, 15, tid);
    cpa_commit();

    // =========================== Phase A: K (i=0..2) then V (i=3..5) prep ===========================
    for (int i = 0; i < 6; i++) {
        int isV = (i >= 3);
        cpa_wait<0>();
        __syncthreads();                        // chunk i arrived; prev epilogue reads of sCS done
        if (i < 3) { stage_cs(sCS, g_csb + i * 1024, tid); cpa_commit(); }     // [A]
        if (i == 3) { stage_w(sW, g_wv, tid); cpa_commit(); }                  // [W]

        // LayerNorm 32 rows
        {
            const float* lng  = isV ? lnvg : lnkg;
            const float* lnb_ = isV ? lnvb : lnkb;
            const float* rp = raw + lrow * 128;
            float vv[16];
            #pragma unroll
            for (int i4 = 0; i4 < 4; i4++) {
                float4 f = *reinterpret_cast<const float4*>(rp + (lsub + 8 * i4) * 4);
                vv[4 * i4] = f.x; vv[4 * i4 + 1] = f.y; vv[4 * i4 + 2] = f.z; vv[4 * i4 + 3] = f.w;
            }
            float s = 0.f;
            #pragma unroll
            for (int i2 = 0; i2 < 16; i2++) s += vv[i2];
            #pragma unroll
            for (int o = 1; o < 8; o <<= 1) s += __shfl_xor_sync(0xffffffffu, s, o);
            float mu = s * (1.0f / 128.0f);
            float q2 = 0.f;
            #pragma unroll
            for (int i2 = 0; i2 < 16; i2++) { float d = vv[i2] - mu; q2 += d * d; }
            #pragma unroll
            for (int o = 1; o < 8; o <<= 1) q2 += __shfl_xor_sync(0xffffffffu, q2, o);
            float rs = rsqrtf(q2 * (1.0f / 128.0f) + 1e-5f);
            unsigned* xw = reinterpret_cast<unsigned*>(sX) + lrow * 68;
            #pragma unroll
            for (int i4 = 0; i4 < 4; i4++) {
                int c0 = lsub * 4 + i4 * 32;
                float a0 = (vv[4 * i4]     - mu) * rs * lng[c0]     + lnb_[c0];
                float a1 = (vv[4 * i4 + 1] - mu) * rs * lng[c0 + 1] + lnb_[c0 + 1];
                float a2 = (vv[4 * i4 + 2] - mu) * rs * lng[c0 + 2] + lnb_[c0 + 2];
                float a3 = (vv[4 * i4 + 3] - mu) * rs * lng[c0 + 3] + lnb_[c0 + 3];
                xw[2 * lsub + 16 * i4]     = pk(a0, a1);
                xw[2 * lsub + 16 * i4 + 1] = pk(a2, a3);
            }
        }
        __syncthreads();                        // raw free, sX ready
        if (i == 3) cpa_wait<0>();              // wv must be resident before GEMM
        // prefetch next chunk into raw
        if (i < 2)       stage_chunk(raw, k, l, (i + 1) * 32, 4, 15, tid);
        else if (i < 5)  stage_chunk(raw, v, l, (i - 2) * 32, 4, 15, tid);
        else             stage_chunk(raw, q, l, 0, 6, 63, tid);
        cpa_commit();

        // GEMM: 32 rows x 128 cols
        float acc[4][4] = {};
        #pragma unroll
        for (int kk = 0; kk < 128; kk += 16) {
            unsigned uoff = ((((kk >> 3) + wu0) ^ wrx) << 4);
            unsigned a[4], b01[4], b23[4];
            ldsm4(a, abase + kk * 2);
            ldsm4(b01, wrow01 + uoff);
            ldsm4(b23, wrow23 + uoff);
            mma16816(acc[0], a, &b01[0]);
            mma16816(acc[1], a, &b01[2]);
            mma16816(acc[2], a, &b23[0]);
            mma16816(acc[3], a, &b23[2]);
        }
        cpa_wait<1>();                          // cs chunk arrived (no-op for V iters)

        if (!isV) {
            // K: +bias -> RoPE(bf16 trig from sCS) -> sK as FP16 (SW64 swizzled)
            #pragma unroll
            for (int r = 0; r < 2; r++) {
                int lt = mrow + gq + 8 * r;
                int t = i * 32 + lt;
                #pragma unroll
                for (int ntl = 0; ntl < 2; ntl++) {
                    int jlo = ntl * 8 + 2 * t4;
                    int jhi = jlo + 16;
                    float2 blo = *reinterpret_cast<const float2*>(&bk[mh * 32 + jlo]);
                    float2 bhi = *reinterpret_cast<const float2*>(&bk[mh * 32 + jhi]);
                    float plo0 = acc[ntl][2 * r] + blo.x;
                    float plo1 = acc[ntl][2 * r + 1] + blo.y;
                    float phi0 = acc[ntl + 2][2 * r] + bhi.x;
                    float phi1 = acc[ntl + 2][2 * r + 1] + bhi.y;
                    uint2 ulo = *reinterpret_cast<const uint2*>(&sCS[lt * 32 + jlo]);
                    uint2 uhi = *reinterpret_cast<const uint2*>(&sCS[lt * 32 + jhi]);
                    float2 cs0 = bf2f(ulo.x), cs1 = bf2f(ulo.y);
                    float2 cs2 = bf2f(uhi.x), cs3 = bf2f(uhi.y);
                    unsigned off0 = t * 64 + jlo * 2;
                    unsigned off1 = t * 64 + jhi * 2;
                    *reinterpret_cast<unsigned*>(sKb + (off0 ^ ((off0 >> 3) & 0x30))) =
                        pkh(plo0 * cs0.x - phi0 * cs0.y, plo1 * cs1.x - phi1 * cs1.y);
                    *reinterpret_cast<unsigned*>(sKb + (off1 ^ ((off1 >> 3) & 0x30))) =
                        pkh(phi0 * cs2.x + plo0 * cs2.y, phi1 * cs3.x + plo1 * cs3.y);
                }
            }
        } else {
            // V: +bias -> transpose into sVt as FP16 (for fp16 PV mma)
            #pragma unroll
            for (int r = 0; r < 2; r++) {
                int t = (i - 3) * 32 + mrow + gq + 8 * r;
                #pragma unroll
                for (int ntl = 0; ntl < 2; ntl++) {
                    int jlo = ntl * 8 + 2 * t4;
                    int jhi = jlo + 16;
                    float2 blo = *reinterpret_cast<const float2*>(&bv[mh * 32 + jlo]);
                    float2 bhi = *reinterpret_cast<const float2*>(&bv[mh * 32 + jhi]);
                    sVtH[(mh * 32 + jlo) * 104 + t]     = __float2half(acc[ntl][2 * r] + blo.x);
                    sVtH[(mh * 32 + jlo + 1) * 104 + t] = __float2half(acc[ntl][2 * r + 1] + blo.y);
                    sVtH[(mh * 32 + jhi) * 104 + t]     = __float2half(acc[ntl + 2][2 * r] + bhi.x);
                    sVtH[(mh * 32 + jhi + 1) * 104 + t] = __float2half(acc[ntl + 2][2 * r + 1] + bhi.y);
                }
            }
        }
    }

    // =========================== Phase B: Q prep + attention + P-accumulation ===========================
    unsigned hxa[12] = {}, hya[12] = {};   // fp16x2 accumulated P-hat (sum over views, /6 folded)
    float oacc[4][4] = {};                 // odd-half O output (fp32)

    for (int j = 0; j < 12; j++) {
        int qc = (j < 6) ? 2 * j : 2 * j - 11;   // even uv-half first, then odd
        cpa_wait<0>();
        __syncthreads();                          // raw_j arrived; prev sCS reads done
        stage_cs(sCS, g_csb + qc * 1024, tid); cpa_commit();
        if (j == 0) { stage_w(sW, g_wq, tid); cpa_commit(); }

        // LayerNorm (q)
        {
            const float* rp = raw + lrow * 128;
            float vv[16];
            #pragma unroll
            for (int i4 = 0; i4 < 4; i4++) {
                float4 f = *reinterpret_cast<const float4*>(rp + (lsub + 8 * i4) * 4);
                vv[4 * i4] = f.x; vv[4 * i4 + 1] = f.y; vv[4 * i4 + 2] = f.z; vv[4 * i4 + 3] = f.w;
            }
            float s = 0.f;
            #pragma unroll
            for (int i2 = 0; i2 < 16; i2++) s += vv[i2];
            #pragma unroll
            for (int o = 1; o < 8; o <<= 1) s += __shfl_xor_sync(0xffffffffu, s, o);
            float mu = s * (1.0f / 128.0f);
            float q2 = 0.f;
            #pragma unroll
            for (int i2 = 0; i2 < 16; i2++) { float d = vv[i2] - mu; q2 += d * d; }
            #pragma unroll
            for (int o = 1; o < 8; o <<= 1) q2 += __shfl_xor_sync(0xffffffffu, q2, o);
            float rs = rsqrtf(q2 * (1.0f / 128.0f) + 1e-5f);
            unsigned* xw = reinterpret_cast<unsigned*>(sX) + lrow * 68;
            #pragma unroll
            for (int i4 = 0; i4 < 4; i4++) {
                int c0 = lsub * 4 + i4 * 32;
                float a0 = (vv[4 * i4]     - mu) * rs * lnqg[c0]     + lnqb[c0];
                float a1 = (vv[4 * i4 + 1] - mu) * rs * lnqg[c0 + 1] + lnqb[c0 + 1];
                float a2 = (vv[4 * i4 + 2] - mu) * rs * lnqg[c0 + 2] + lnqb[c0 + 2];
                float a3 = (vv[4 * i4 + 3] - mu) * rs * lnqg[c0 + 3] + lnqb[c0 + 3];
                xw[2 * lsub + 16 * i4]     = pk(a0, a1);
                xw[2 * lsub + 16 * i4 + 1] = pk(a2, a3);
            }
        }
        __syncthreads();
        if (j == 0) cpa_wait<0>();              // wq resident before GEMM
        if (j < 11) {
            int j2 = j + 1;
            int qc2 = (j2 < 6) ? 2 * j2 : 2 * j2 - 11;
            stage_chunk(raw, q, l, qc2 * 32, 6, 63, tid);
            cpa_commit();
        }

        // q GEMM
        float acc[4][4] = {};
        #pragma unroll
        for (int kk = 0; kk < 128; kk += 16) {
            unsigned uoff = ((((kk >> 3) + wu0) ^ wrx) << 4);
            unsigned a[4], b01[4], b23[4];
            ldsm4(a, abase + kk * 2);
            ldsm4(b01, wrow01 + uoff);
            ldsm4(b23, wrow23 + uoff);
            mma16816(acc[0], a, &b01[0]);
            mma16816(acc[1], a, &b01[2]);
            mma16816(acc[2], a, &b23[0]);
            mma16816(acc[3], a, &b23[2]);
        }
        if (j < 11) cpa_wait<1>(); else cpa_wait<0>();   // cs arrived

        // epilogue: +bias -> RoPE(bf16 trig) -> *scale(log2e folded) -> FP16 A fragments
        unsigned aq0[4], aq1[4];
        {
            float F[4][4];
            #pragma unroll
            for (int r = 0; r < 2; r++) {
                int lt = mrow + gq + 8 * r;
                #pragma unroll
                for (int ntl = 0; ntl < 2; ntl++) {
                    int jlo = ntl * 8 + 2 * t4;
                    int jhi = jlo + 16;
                    float2 blo = *reinterpret_cast<const float2*>(&bq[mh * 32 + jlo]);
                    float2 bhi = *reinterpret_cast<const float2*>(&bq[mh * 32 + jhi]);
                    float plo0 = acc[ntl][2 * r] + blo.x;
                    float plo1 = acc[ntl][2 * r + 1] + blo.y;
                    float phi0 = acc[ntl + 2][2 * r] + bhi.x;
                    float phi1 = acc[ntl + 2][2 * r + 1] + bhi.y;
                    uint2 ulo = *reinterpret_cast<const uint2*>(&sCS[lt * 32 + jlo]);
                    uint2 uhi = *reinterpret_cast<const uint2*>(&sCS[lt * 32 + jhi]);
                    float2 cs0 = bf2f(ulo.x), cs1 = bf2f(ulo.y);
                    float2 cs2 = bf2f(uhi.x), cs3 = bf2f(uhi.y);
                    F[ntl][2 * r]         = (plo0 * cs0.x - phi0 * cs0.y) * sc;
                    F[ntl][2 * r + 1]     = (plo1 * cs1.x - phi1 * cs1.y) * sc;
                    F[ntl + 2][2 * r]     = (phi0 * cs2.x + plo0 * cs2.y) * sc;
                    F[ntl + 2][2 * r + 1] = (phi1 * cs3.x + plo1 * cs3.y) * sc;
                }
            }
            aq0[0] = pkh(F[0][0], F[0][1]); aq0[1] = pkh(F[0][2], F[0][3]);
            aq0[2] = pkh(F[1][0], F[1][1]); aq0[3] = pkh(F[1][2], F[1][3]);
            aq1[0] = pkh(F[2][0], F[2][1]); aq1[1] = pkh(F[2][2], F[2][3]);
            aq1[2] = pkh(F[3][0], F[3][1]); aq1[3] = pkh(F[3][2], F[3][3]);
        }

        // S = Q K^T over 96 keys (fp16 accumulators; D pairs == softmax pair layout)
        unsigned sacc2[12][2] = {};
        #pragma unroll
        for (int p = 0; p < 6; p++) {
            unsigned b[4];
            ldsm4(b, kb0[p]);
            mma16816hh(sacc2[2 * p], aq0, &b[0]);
            mma16816hh(sacc2[2 * p + 1], aq0, &b[2]);
        }
        #pragma unroll
        for (int p = 0; p < 6; p++) {
            unsigned b[4];
            ldsm4(b, kb0[p] ^ 32u);
            mma16816hh(sacc2[2 * p], aq1, &b[0]);
            mma16816hh(sacc2[2 * p + 1], aq1, &b[2]);
        }

        // fp16x2 softmax; normalized P accumulated into hxa/hya via HFMA2 (1/6 folded)
        unsigned hx[12], hy[12];
        #pragma unroll
        for (int nt = 0; nt < 12; nt++) {
            hx[nt] = ex2h2(sacc2[nt][0]);
            hy[nt] = ex2h2(sacc2[nt][1]);
        }
        __half2 s2x = u2h(hx[0]), s2y = u2h(hy[0]);
        #pragma unroll
        for (int nt = 1; nt < 12; nt++) {
            s2x = __hadd2(s2x, u2h(hx[nt]));
            s2y = __hadd2(s2y, u2h(hy[nt]));
        }
        float sm0 = __low2float(s2x) + __high2float(s2x);
        float sm1 = __low2float(s2y) + __high2float(s2y);
        sm0 += __shfl_xor_sync(0xffffffffu, sm0, 1);
        sm0 += __shfl_xor_sync(0xffffffffu, sm0, 2);
        sm1 += __shfl_xor_sync(0xffffffffu, sm1, 1);
        sm1 += __shfl_xor_sync(0xffffffffu, sm1, 2);
        float r0i = __fdividef(0.16666667f, sm0);
        float r1i = __fdividef(0.16666667f, sm1);
        __half2 h2r0 = u2h(cvth2(r0i, r0i));
        __half2 h2r1 = u2h(cvth2(r1i, r1i));
        #pragma unroll
        for (int nt = 0; nt < 12; nt++) {
            hxa[nt] = h2u(__hfma2(u2h(hx[nt]), h2r0, u2h(hxa[nt])));
            hya[nt] = h2u(__hfma2(u2h(hy[nt]), h2r1, u2h(hya[nt])));
        }

        if (j == 5) {
            // single PV over view-summed P-hat for even uv-half -> g_tmp
            float ofl[4][4] = {};
            #pragma unroll
            for (int c6 = 0; c6 < 6; c6++) {
                unsigned a[4];
                a[0] = hxa[2 * c6];
                a[1] = hya[2 * c6];
                a[2] = hxa[2 * c6 + 1];
                a[3] = hya[2 * c6 + 1];
                #pragma unroll
                for (int p = 0; p < 2; p++) {
                    unsigned b[4];
                    ldsm4(b, vb[p] + c6 * 32);
                    mma16816h(ofl[2 * p], a, &b[0]);
                    mma16816h(ofl[2 * p + 1], a, &b[2]);
                }
            }
            #pragma unroll
            for (int nt = 0; nt < 4; nt++) {
                int col = mh * 32 + nt * 8 + 2 * t4;
                #pragma unroll
                for (int r = 0; r < 2; r++) {
                    int uv = mrow + gq + 8 * r;
                    *reinterpret_cast<unsigned*>(g_tmp + (size_t)l * 4096 + uv * 128 + col) =
                        pk(ofl[nt][2 * r], ofl[nt][2 * r + 1]);
                }
            }
            #pragma unroll
            for (int nt = 0; nt < 12; nt++) { hxa[nt] = 0u; hya[nt] = 0u; }
        } else if (j == 11) {
            // single PV for odd uv-half -> oacc (kept in registers for Phase C)
            #pragma unroll
            for (int c6 = 0; c6 < 6; c6++) {
                unsigned a[4];
                a[0] = hxa[2 * c6];
                a[1] = hya[2 * c6];
                a[2] = hxa[2 * c6 + 1];
                a[3] = hya[2 * c6 + 1];
                #pragma unroll
                for (int p = 0; p < 2; p++) {
                    unsigned b[4];
                    ldsm4(b, vb[p] + c6 * 32);
                    mma16816h(oacc[2 * p], a, &b[0]);
                    mma16816h(oacc[2 * p + 1], a, &b[2]);
                }
            }
        }
    }

    // =========================== Phase C: mean -> proj -> +skip -> out ===========================
    __syncthreads();   // all attention reads of sK/sVt/sW/raw done

    // odd uv-half: registers -> rawO rows 32..63 (swizzled bf16 64x128)
    #pragma unroll
    for (int nt = 0; nt < 4; nt++) {
        int col = mh * 32 + nt * 8 + 2 * t4;
        int cu = col >> 3;
        #pragma unroll
        for (int r = 0; r < 2; r++) {
            int row = 32 + mrow + gq + 8 * r;
            *reinterpret_cast<unsigned*>(&rawO[row * 128 + ((cu ^ (row & 7)) << 3) + (col & 7)]) =
                pk(oacc[nt][2 * r], oacc[nt][2 * r + 1]);
        }
    }
    // stage wp, even uv-half (g_tmp), skip
    stage_w(sW, g_wp, tid);
    #pragma unroll
    for (int u = tid; u < 512; u += 256) {
        int row = u >> 4, cu = u & 15;
        cpa16(&rawO[row * 128 + ((cu ^ (row & 7)) << 3)],
              g_tmp + (size_t)l * 4096 + row * 128 + cu * 8);
    }
    float* sSkip = reinterpret_cast<float*>(sm + E_K);   // 32 KB inside dead sK/sVt region
    #pragma unroll
    for (int u = tid; u < 2048; u += 256)
        cpa16(sSkip + u * 4, skip + (size_t)l * 8192 + u * 4);
    cpa_commit();
    cpa_wait<0>();
    __syncthreads();

    // proj GEMM: 64 rows x 128 cols
    {
        int rh = wid & 3, cg = wid >> 2;
        int prowA = rh * 16 + (lane & 15);
        unsigned paRow = ssa(rawO) + prowA * 256;
        int parx = prowA & 7, pau0 = lane >> 4;
        int op = cg * 64 + ((lane >> 4) << 3) + (lane & 7);
        unsigned pw0 = sWb + op * 256;
        int prx = op & 7;
        float pacc[8][4] = {};
        #pragma unroll
        for (int kk = 0; kk < 128; kk += 16) {
            unsigned a[4];
            ldsm4(a, paRow + ((((kk >> 3) + pau0) ^ parx) << 4));
            unsigned uoff = ((((kk >> 3) + wu0) ^ prx) << 4);
            #pragma unroll
            for (int p = 0; p < 4; p++) {
                unsigned b[4];
                ldsm4(b, pw0 + p * 4096 + uoff);
                mma16816(pacc[2 * p], a, &b[0]);
                mma16816(pacc[2 * p + 1], a, &b[2]);
            }
        }
        #pragma unroll
        for (int nt = 0; nt < 8; nt++) {
            int col = cg * 64 + nt * 8 + 2 * t4;
            float2 bp = *reinterpret_cast<const float2*>(&bproj[col]);
            #pragma unroll
            for (int r = 0; r < 2; r++) {
                int rloc = rh * 16 + gq + 8 * r;
                float2 sk = *reinterpret_cast<const float2*>(sSkip + rloc * 128 + col);
                float2 o2;
                o2.x = pacc[nt][2 * r] + bp.x + sk.x;
                o2.y = pacc[nt][2 * r + 1] + bp.y + sk.y;
                *reinterpret_cast<float2*>(out + ((size_t)l * 64 + rloc) * 128 + col) = o2;
            }
        }
    }
}

// ---------------- launch ----------------
extern "C" void kernel_launch(void* const* d_in, const int* in_sizes, int n_in,
                              void* d_out, int out_size) {
    const float* q     = (const float*)d_in[0];
    const float* k     = (const float*)d_in[1];
    const float* v     = (const float*)d_in[2];
    const float* skip  = (const float*)d_in[3];
    const float* freqs = (const float*)d_in[4];
    const float* gate  = (const float*)d_in[5];
    const float* lnqg  = (const float*)d_in[6];
    const float* lnqb  = (const float*)d_in[7];
    const float* lnkg  = (const float*)d_in[8];
    const float* lnkb  = (const float*)d_in[9];
    const float* lnvg  = (const float*)d_in[10];
    const float* lnvb  = (const float*)d_in[11];
    const float* wq    = (const float*)d_in[12];
    const float* bq    = (const float*)d_in[13];
    const float* wk    = (const float*)d_in[14];
    const float* bk    = (const float*)d_in[15];
    const float* wv    = (const float*)d_in[16];
    const float* bv    = (const float*)d_in[17];
    const float* wproj = (const float*)d_in[18];
    const float* bproj = (const float*)d_in[19];
    const float* als   = (const float*)d_in[20];
    float* out = (float*)d_out;

    static int smem_set = 0;
    if (!smem_set) {
        cudaFuncSetAttribute(fused_kernel, cudaFuncAttributeMaxDynamicSharedMemorySize, SMEM_BYTES);
        smem_set = 1;
    }

    prep_const_kernel<<<305, 256>>>(wq, wk, wv, wproj, freqs, gate, als);
    fused_kernel<<<LTOT, 256, SMEM_BYTES>>>(q, k, v, skip,
                                            lnqg, lnqb, lnkg, lnkb, lnvg, lnvb,
                                            bq, bk, bv, bproj, out);
}

// round 17
// speedup vs baseline: 1.0750x; 1.0170x over previous
#include <cuda_runtime.h>
#include <cuda_bf16.h>
#include <cuda_fp16.h>
#include <math.h>

// ---------------- problem constants ----------------
// B=1, N=6, X=Y=25 (L=625), W1=W2=8 (Qn=384), w1=w2=4 (Kn=96), D=128, M=4 heads, dh=32

#define LTOT 625
#define QN   384

// ---------------- device constants / scratch ----------------
__device__ __half        g_wqh[16384];   // wq as fp16 (Phase B hh mma)
__device__ __nv_bfloat16 g_wk[16384];
__device__ __nv_bfloat16 g_wv[16384];
__device__ __nv_bfloat16 g_wp[16384];
__device__ __nv_bfloat16 g_tmp[(size_t)LTOT * 32 * 128];   // even-half O-mean spill
__device__ unsigned g_csb[QN * 32];      // packed bf16x2 (cos, sin) — Phase A
__device__ unsigned g_cspu[QN * 32];     // Phase B: [t*32 + jp*2] = fp16x2 cos-pair, +1 = sin-pair
__device__ unsigned g_bqh[64];           // packed fp16x2 bq pairs (4 heads x 16)
__device__ float g_scales[4];

// ---------------- helpers ----------------
__device__ __forceinline__ unsigned pk(float a, float b) {
    __nv_bfloat162 h = __floats2bfloat162_rn(a, b);
    return *reinterpret_cast<unsigned*>(&h);
}
__device__ __forceinline__ float2 bf2f(unsigned u) {
    __nv_bfloat162 h = *reinterpret_cast<__nv_bfloat162*>(&u);
    return __bfloat1622float2(h);
}
__device__ __forceinline__ __half2 u2h(unsigned u) {
    return *reinterpret_cast<__half2*>(&u);
}
__device__ __forceinline__ unsigned h2u(__half2 h) {
    return *reinterpret_cast<unsigned*>(&h);
}
// pack two f32 into f16x2: first arg -> HIGH half, second -> LOW half
__device__ __forceinline__ unsigned cvth2(float hi, float lo) {
    unsigned d;
    asm("cvt.rn.f16x2.f32 %0, %1, %2;\n" : "=r"(d) : "f"(hi), "f"(lo));
    return d;
}
// fp16 pack with (lo, hi) argument order matching pk()
__device__ __forceinline__ unsigned pkh(float lo, float hi) {
    return cvth2(hi, lo);
}
__device__ __forceinline__ unsigned ex2h2(unsigned x) {
    unsigned y;
    asm("ex2.approx.f16x2 %0, %1;\n" : "=r"(y) : "r"(x));
    return y;
}
__device__ __forceinline__ unsigned ssa(const void* p) {
    return (unsigned)__cvta_generic_to_shared(p);
}
__device__ __forceinline__ void ldsm4(unsigned r[4], unsigned addr) {
    asm volatile("ldmatrix.sync.aligned.m8n8.x4.shared.b16 {%0,%1,%2,%3}, [%4];\n"
                 : "=r"(r[0]), "=r"(r[1]), "=r"(r[2]), "=r"(r[3]) : "r"(addr));
}
// bf16 mma, fp32 accum
__device__ __forceinline__ void mma16816(float c[4], const unsigned a[4], const unsigned b[2]) {
    asm volatile(
        "mma.sync.aligned.m16n8k16.row.col.f32.bf16.bf16.f32 "
        "{%0,%1,%2,%3}, {%4,%5,%6,%7}, {%8,%9}, {%0,%1,%2,%3};\n"
        : "+f"(c[0]), "+f"(c[1]), "+f"(c[2]), "+f"(c[3])
        : "r"(a[0]), "r"(a[1]), "r"(a[2]), "r"(a[3]), "r"(b[0]), "r"(b[1]));
}
// fp16 mma, fp32 accum (for P*V)
__device__ __forceinline__ void mma16816h(float c[4], const unsigned a[4], const unsigned b[2]) {
    asm volatile(
        "mma.sync.aligned.m16n8k16.row.col.f32.f16.f16.f32 "
        "{%0,%1,%2,%3}, {%4,%5,%6,%7}, {%8,%9}, {%0,%1,%2,%3};\n"
        : "+f"(c[0]), "+f"(c[1]), "+f"(c[2]), "+f"(c[3])
        : "r"(a[0]), "r"(a[1]), "r"(a[2]), "r"(a[3]), "r"(b[0]), "r"(b[1]));
}
// fp16 mma, fp16 accum: D = 2 packed f16x2 regs (row gq pair / row gq+8 pair)
__device__ __forceinline__ void mma16816hh(unsigned c[2], const unsigned a[4], const unsigned b[2]) {
    asm volatile(
        "mma.sync.aligned.m16n8k16.row.col.f16.f16.f16.f16 "
        "{%0,%1}, {%2,%3,%4,%5}, {%6,%7}, {%0,%1};\n"
        : "+r"(c[0]), "+r"(c[1])
        : "r"(a[0]), "r"(a[1]), "r"(a[2]), "r"(a[3]), "r"(b[0]), "r"(b[1]));
}
__device__ __forceinline__ void cpa16(void* dst, const void* src) {
    asm volatile("cp.async.cg.shared.global [%0], [%1], 16;\n"
                 :: "r"(ssa(dst)), "l"(src));
}
__device__ __forceinline__ void cpa_commit() {
    asm volatile("cp.async.commit_group;\n");
}
template<int N> __device__ __forceinline__ void cpa_wait() {
    asm volatile("cp.async.wait_group %0;\n" :: "n"(N));
}

// ---------------- kernel 0: constants prep ----------------
__global__ __launch_bounds__(256) void prep_const_kernel(
    const float* __restrict__ wq, const float* __restrict__ wk,
    const float* __restrict__ wv, const float* __restrict__ wp,
    const float* __restrict__ freqs, const float* __restrict__ gate,
    const float* __restrict__ als, const float* __restrict__ bq)
{
    int idx = blockIdx.x * 256 + threadIdx.x;
    if (idx < 16384) {
        g_wqh[idx] = __float2half(wq[idx]);
    } else if (idx < 32768) {
        g_wk[idx - 16384] = __float2bfloat16(wk[idx - 16384]);
    } else if (idx < 49152) {
        g_wv[idx - 32768] = __float2bfloat16(wv[idx - 32768]);
    } else if (idx < 65536) {
        g_wp[idx - 49152] = __float2bfloat16(wp[idx - 49152]);
    } else if (idx < 65536 + QN * 32) {
        int j = idx - 65536;
        float f = freqs[j];            // (400,32) row-major, t<384 prefix
        g_csb[j] = pk(cosf(f), sinf(f));
    } else if (idx < 65536 + QN * 32 + 4) {
        int m = idx - (65536 + QN * 32);
        float temp = als[m] - 0.5f * logf(32.0f);   // als + log(dh^-0.5)
        float ga = fminf(fmaxf(gate[m], 0.0f), 1.0f);
        g_scales[m] = temp * ga * 1.44269504f;      // fold log2(e): ex2 later
    } else if (idx < 65536 + QN * 32 + 4 + QN * 16) {
        int e = idx - (65536 + QN * 32 + 4);
        int t = e >> 4, jp = e & 15;
        float f0 = freqs[t * 32 + 2 * jp];
        float f1 = freqs[t * 32 + 2 * jp + 1];
        g_cspu[t * 32 + jp * 2]     = cvth2(cosf(f1), cosf(f0));
        g_cspu[t * 32 + jp * 2 + 1] = cvth2(sinf(f1), sinf(f0));
    } else if (idx < 65536 + QN * 32 + 4 + QN * 16 + 64) {
        int e = idx - (65536 + QN * 32 + 4 + QN * 16);
        int m = e >> 4, jp = e & 15;
        g_bqh[e] = cvth2(bq[m * 32 + 2 * jp + 1], bq[m * 32 + 2 * jp]);
    }
}

// ---------------- smem layout (bf16 element offsets) ----------------
// sK   : 4*96*32 = 12288   K per head (FP16), SW64-XOR-swizzled (64B rows)
// sVt  : 4*32*104 = 13312  V^T[d][s] (fp16) padded stride 104, per head
// sW   : 128*128 = 16384   weights, XOR-swizzled 16B units
// raw  : 8192 elems (16 KB) fp32 LN staging 32x128; Phase C: bf16 O 64x128 swizzled
// sCS  : 2048 elems (4 KB)  trig table for current 32-row chunk (format per phase)
// sX   : 32*136 = 4352     LN output staging (bf16 in A, fp16 in B)
#define E_K   0
#define E_VT  12288
#define E_W   25600
#define E_RAW 41984
#define E_CS  50176
#define E_X   52224
#define SMEM_ELEMS 56576
#define SMEM_BYTES (SMEM_ELEMS * 2)   // 113152 -> 2 blocks/SM

__device__ __forceinline__ void stage_w(__nv_bfloat16* sW, const __nv_bfloat16* w, int tid) {
    #pragma unroll
    for (int u = tid; u < 2048; u += 256) {
        int row = u >> 4, cu = u & 15;
        cpa16(sW + row * 128 + ((cu ^ (row & 7)) << 3), w + u * 8);
    }
}
__device__ __forceinline__ void stage_chunk(float* raw, const float* x, int l,
                                            int t0, int sh, int msk, int tid) {
    #pragma unroll
    for (int j = 0; j < 4; j++) {
        int idx = tid + 256 * j;
        int row = idx >> 5, c4 = idx & 31;
        int t = t0 + row;
        int n = t >> sh, rem = t & msk;
        cpa16(raw + row * 128 + c4 * 4,
              x + ((size_t)(n * LTOT + l) * (msk + 1) + rem) * 128 + c4 * 4);
    }
}
__device__ __forceinline__ void stage_cs(unsigned* sCS, const unsigned* src, int tid) {
    cpa16(sCS + tid * 4, src + tid * 4);   // 256 threads x 16B = 4 KB
}

// ---------------- fused kernel: one block per l-tile, 2 blocks/SM ----------------
__global__ __launch_bounds__(256, 2) void fused_kernel(
    const float* __restrict__ q, const float* __restrict__ k,
    const float* __restrict__ v, const float* __restrict__ skip,
    const float* __restrict__ lnqg, const float* __restrict__ lnqb,
    const float* __restrict__ lnkg, const float* __restrict__ lnkb,
    const float* __restrict__ lnvg, const float* __restrict__ lnvb,
    const float* __restrict__ bk,
    const float* __restrict__ bv, const float* __restrict__ bproj,
    float* __restrict__ out)
{
    extern __shared__ __nv_bfloat16 sm[];
    __nv_bfloat16* sK  = sm + E_K;
    __nv_bfloat16* sVt = sm + E_VT;
    __nv_bfloat16* sW  = sm + E_W;
    float* raw = reinterpret_cast<float*>(sm + E_RAW);
    __nv_bfloat16* rawO = sm + E_RAW;
    unsigned* sCS = reinterpret_cast<unsigned*>(sm + E_CS);
    __nv_bfloat16* sX  = sm + E_X;
    __half* sVtH = reinterpret_cast<__half*>(sVt);

    int l = blockIdx.x;
    int tid = threadIdx.x;
    int wid = tid >> 5, lane = tid & 31, gq = lane >> 2, t4 = lane & 3;
    int mrow = (wid & 1) * 16;            // 16-row half within 32-row chunk
    int mh = wid >> 1;                    // head
    int lrow = tid >> 3, lsub = tid & 7;  // LN: 8 threads/row

    unsigned sWb = ssa(sW);
    unsigned abase = ssa(&sX[(mrow + (lane & 15)) * 136 + ((lane >> 4) << 3)]);

    // weight B-fragment lane constants (swizzled sW; 16B units, row stride 256 B)
    int o01 = mh * 32 + ((lane >> 4) << 3) + (lane & 7);
    unsigned wrow01 = sWb + o01 * 256;
    unsigned wrow23 = wrow01 + 4096;      // +16 output rows
    int wrx = o01 & 7;
    int wu0 = (lane >> 3) & 1;

    // K fragment bases (SW64-swizzled sK): second kk block = addr ^ 32
    char* sKb = reinterpret_cast<char*>(sK) + mh * 6144;
    unsigned kb0[6];
    {
        unsigned sKhb = ssa(sKb);
        int u0 = (lane >> 3) & 1;
        #pragma unroll
        for (int p = 0; p < 6; p++) {
            int tr = (2 * p + (lane >> 4)) * 8 + (lane & 7);
            kb0[p] = sKhb + tr * 64 + ((u0 ^ ((tr >> 1) & 3)) << 4);
        }
    }
    // V^T fragment bases (padded stride 104)
    __nv_bfloat16* sVh = sVt + mh * 32 * 104;
    unsigned vb[2];
    #pragma unroll
    for (int p = 0; p < 2; p++)
        vb[p] = ssa(&sVh[((2 * p + (lane >> 4)) * 8 + (lane & 7)) * 104 + (((lane >> 3) & 1) << 3)]);
    float sc = g_scales[mh];
    __half2 sc2 = u2h(cvth2(sc, sc));

    // initial: wk + first k chunk
    stage_w(sW, g_wk, tid);
    cpa_commit();
    stage_chunk(raw, k, l, 0, 4, 15, tid);
    cpa_commit();

    // =========================== Phase A: K (i=0..2) then V (i=3..5) prep ===========================
    for (int i = 0; i < 6; i++) {
        int isV = (i >= 3);
        cpa_wait<0>();
        __syncthreads();                        // chunk i arrived; prev epilogue reads of sCS done
        if (i < 3) { stage_cs(sCS, g_csb + i * 1024, tid); cpa_commit(); }     // [A]
        if (i == 3) { stage_w(sW, g_wv, tid); cpa_commit(); }                  // [W]

        // LayerNorm 32 rows
        {
            const float* lng  = isV ? lnvg : lnkg;
            const float* lnb_ = isV ? lnvb : lnkb;
            const float* rp = raw + lrow * 128;
            float vv[16];
            #pragma unroll
            for (int i4 = 0; i4 < 4; i4++) {
                float4 f = *reinterpret_cast<const float4*>(rp + (lsub + 8 * i4) * 4);
                vv[4 * i4] = f.x; vv[4 * i4 + 1] = f.y; vv[4 * i4 + 2] = f.z; vv[4 * i4 + 3] = f.w;
            }
            float s = 0.f;
            #pragma unroll
            for (int i2 = 0; i2 < 16; i2++) s += vv[i2];
            #pragma unroll
            for (int o = 1; o < 8; o <<= 1) s += __shfl_xor_sync(0xffffffffu, s, o);
            float mu = s * (1.0f / 128.0f);
            float q2 = 0.f;
            #pragma unroll
            for (int i2 = 0; i2 < 16; i2++) { float d = vv[i2] - mu; q2 += d * d; }
            #pragma unroll
            for (int o = 1; o < 8; o <<= 1) q2 += __shfl_xor_sync(0xffffffffu, q2, o);
            float rs = rsqrtf(q2 * (1.0f / 128.0f) + 1e-5f);
            unsigned* xw = reinterpret_cast<unsigned*>(sX) + lrow * 68;
            #pragma unroll
            for (int i4 = 0; i4 < 4; i4++) {
                int c0 = lsub * 4 + i4 * 32;
                float a0 = (vv[4 * i4]     - mu) * rs * lng[c0]     + lnb_[c0];
                float a1 = (vv[4 * i4 + 1] - mu) * rs * lng[c0 + 1] + lnb_[c0 + 1];
                float a2 = (vv[4 * i4 + 2] - mu) * rs * lng[c0 + 2] + lnb_[c0 + 2];
                float a3 = (vv[4 * i4 + 3] - mu) * rs * lng[c0 + 3] + lnb_[c0 + 3];
                xw[2 * lsub + 16 * i4]     = pk(a0, a1);
                xw[2 * lsub + 16 * i4 + 1] = pk(a2, a3);
            }
        }
        __syncthreads();                        // raw free, sX ready
        if (i == 3) cpa_wait<0>();              // wv must be resident before GEMM
        // prefetch next chunk into raw
        if (i < 2)       stage_chunk(raw, k, l, (i + 1) * 32, 4, 15, tid);
        else if (i < 5)  stage_chunk(raw, v, l, (i - 2) * 32, 4, 15, tid);
        else             stage_chunk(raw, q, l, 0, 6, 63, tid);
        cpa_commit();

        // GEMM: 32 rows x 128 cols (bf16)
        float acc[4][4] = {};
        #pragma unroll
        for (int kk = 0; kk < 128; kk += 16) {
            unsigned uoff = ((((kk >> 3) + wu0) ^ wrx) << 4);
            unsigned a[4], b01[4], b23[4];
            ldsm4(a, abase + kk * 2);
            ldsm4(b01, wrow01 + uoff);
            ldsm4(b23, wrow23 + uoff);
            mma16816(acc[0], a, &b01[0]);
            mma16816(acc[1], a, &b01[2]);
            mma16816(acc[2], a, &b23[0]);
            mma16816(acc[3], a, &b23[2]);
        }
        cpa_wait<1>();                          // cs chunk arrived (no-op for V iters)

        if (!isV) {
            // K: +bias -> RoPE(bf16 trig from sCS) -> sK as FP16 (SW64 swizzled)
            #pragma unroll
            for (int r = 0; r < 2; r++) {
                int lt = mrow + gq + 8 * r;
                int t = i * 32 + lt;
                #pragma unroll
                for (int ntl = 0; ntl < 2; ntl++) {
                    int jlo = ntl * 8 + 2 * t4;
                    int jhi = jlo + 16;
                    float2 blo = *reinterpret_cast<const float2*>(&bk[mh * 32 + jlo]);
                    float2 bhi = *reinterpret_cast<const float2*>(&bk[mh * 32 + jhi]);
                    float plo0 = acc[ntl][2 * r] + blo.x;
                    float plo1 = acc[ntl][2 * r + 1] + blo.y;
                    float phi0 = acc[ntl + 2][2 * r] + bhi.x;
                    float phi1 = acc[ntl + 2][2 * r + 1] + bhi.y;
                    uint2 ulo = *reinterpret_cast<const uint2*>(&sCS[lt * 32 + jlo]);
                    uint2 uhi = *reinterpret_cast<const uint2*>(&sCS[lt * 32 + jhi]);
                    float2 cs0 = bf2f(ulo.x), cs1 = bf2f(ulo.y);
                    float2 cs2 = bf2f(uhi.x), cs3 = bf2f(uhi.y);
                    unsigned off0 = t * 64 + jlo * 2;
                    unsigned off1 = t * 64 + jhi * 2;
                    *reinterpret_cast<unsigned*>(sKb + (off0 ^ ((off0 >> 3) & 0x30))) =
                        pkh(plo0 * cs0.x - phi0 * cs0.y, plo1 * cs1.x - phi1 * cs1.y);
                    *reinterpret_cast<unsigned*>(sKb + (off1 ^ ((off1 >> 3) & 0x30))) =
                        pkh(phi0 * cs2.x + plo0 * cs2.y, phi1 * cs3.x + plo1 * cs3.y);
                }
            }
        } else {
            // V: +bias -> transpose into sVt as FP16 (for fp16 PV mma)
            #pragma unroll
            for (int r = 0; r < 2; r++) {
                int t = (i - 3) * 32 + mrow + gq + 8 * r;
                #pragma unroll
                for (int ntl = 0; ntl < 2; ntl++) {
                    int jlo = ntl * 8 + 2 * t4;
                    int jhi = jlo + 16;
                    float2 blo = *reinterpret_cast<const float2*>(&bv[mh * 32 + jlo]);
                    float2 bhi = *reinterpret_cast<const float2*>(&bv[mh * 32 + jhi]);
                    sVtH[(mh * 32 + jlo) * 104 + t]     = __float2half(acc[ntl][2 * r] + blo.x);
                    sVtH[(mh * 32 + jlo + 1) * 104 + t] = __float2half(acc[ntl][2 * r + 1] + blo.y);
                    sVtH[(mh * 32 + jhi) * 104 + t]     = __float2half(acc[ntl + 2][2 * r] + bhi.x);
                    sVtH[(mh * 32 + jhi + 1) * 104 + t] = __float2half(acc[ntl + 2][2 * r + 1] + bhi.y);
                }
            }
        }
    }

    // =========================== Phase B: Q prep + attention + P-accumulation ===========================
    unsigned hxa[12] = {}, hya[12] = {};   // fp16x2 accumulated P-hat (sum over views, /6 folded)
    float oacc[4][4] = {};                 // odd-half O output (fp32)

    for (int j = 0; j < 12; j++) {
        int qc = (j < 6) ? 2 * j : 2 * j - 11;   // even uv-half first, then odd
        cpa_wait<0>();
        __syncthreads();                          // raw_j arrived; prev sCS reads done
        stage_cs(sCS, g_cspu + qc * 1024, tid); cpa_commit();   // Phase-B trig format
        if (j == 0) { stage_w(sW, reinterpret_cast<const __nv_bfloat16*>(g_wqh), tid); cpa_commit(); }

        // LayerNorm (q) -> FP16 output (for hh mma)
        {
            const float* rp = raw + lrow * 128;
            float vv[16];
            #pragma unroll
            for (int i4 = 0; i4 < 4; i4++) {
                float4 f = *reinterpret_cast<const float4*>(rp + (lsub + 8 * i4) * 4);
                vv[4 * i4] = f.x; vv[4 * i4 + 1] = f.y; vv[4 * i4 + 2] = f.z; vv[4 * i4 + 3] = f.w;
            }
            float s = 0.f;
            #pragma unroll
            for (int i2 = 0; i2 < 16; i2++) s += vv[i2];
            #pragma unroll
            for (int o = 1; o < 8; o <<= 1) s += __shfl_xor_sync(0xffffffffu, s, o);
            float mu = s * (1.0f / 128.0f);
            float q2 = 0.f;
            #pragma unroll
            for (int i2 = 0; i2 < 16; i2++) { float d = vv[i2] - mu; q2 += d * d; }
            #pragma unroll
            for (int o = 1; o < 8; o <<= 1) q2 += __shfl_xor_sync(0xffffffffu, q2, o);
            float rs = rsqrtf(q2 * (1.0f / 128.0f) + 1e-5f);
            unsigned* xw = reinterpret_cast<unsigned*>(sX) + lrow * 68;
            #pragma unroll
            for (int i4 = 0; i4 < 4; i4++) {
                int c0 = lsub * 4 + i4 * 32;
                float a0 = (vv[4 * i4]     - mu) * rs * lnqg[c0]     + lnqb[c0];
                float a1 = (vv[4 * i4 + 1] - mu) * rs * lnqg[c0 + 1] + lnqb[c0 + 1];
                float a2 = (vv[4 * i4 + 2] - mu) * rs * lnqg[c0 + 2] + lnqb[c0 + 2];
                float a3 = (vv[4 * i4 + 3] - mu) * rs * lnqg[c0 + 3] + lnqb[c0 + 3];
                xw[2 * lsub + 16 * i4]     = pkh(a0, a1);
                xw[2 * lsub + 16 * i4 + 1] = pkh(a2, a3);
            }
        }
        __syncthreads();
        if (j == 0) cpa_wait<0>();              // wq resident before GEMM
        if (j < 11) {
            int j2 = j + 1;
            int qc2 = (j2 < 6) ? 2 * j2 : 2 * j2 - 11;
            stage_chunk(raw, q, l, qc2 * 32, 6, 63, tid);
            cpa_commit();
        }

        // q GEMM: fp16 accumulate (acc pairs land in softmax pair layout)
        unsigned acc2q[4][2] = {};
        #pragma unroll
        for (int kk = 0; kk < 128; kk += 16) {
            unsigned uoff = ((((kk >> 3) + wu0) ^ wrx) << 4);
            unsigned a[4], b01[4], b23[4];
            ldsm4(a, abase + kk * 2);
            ldsm4(b01, wrow01 + uoff);
            ldsm4(b23, wrow23 + uoff);
            mma16816hh(acc2q[0], a, &b01[0]);
            mma16816hh(acc2q[1], a, &b01[2]);
            mma16816hh(acc2q[2], a, &b23[0]);
            mma16816hh(acc2q[3], a, &b23[2]);
        }
        if (j < 11) cpa_wait<1>(); else cpa_wait<0>();   // cs arrived

        // packed fp16 epilogue: +bias -> RoPE -> *scale -> A fragments
        unsigned aq0[4], aq1[4];
        #pragma unroll
        for (int ntl = 0; ntl < 2; ntl++) {
            int jp = ntl * 4 + t4;
            __half2 blo = u2h(g_bqh[mh * 16 + jp]);
            __half2 bhi = u2h(g_bqh[mh * 16 + jp + 8]);
            #pragma unroll
            for (int r = 0; r < 2; r++) {
                int lt = mrow + gq + 8 * r;
                uint2 cl = *reinterpret_cast<const uint2*>(&sCS[lt * 32 + jp * 2]);
                uint2 ch = *reinterpret_cast<const uint2*>(&sCS[lt * 32 + (jp + 8) * 2]);
                __half2 pl = __hadd2(u2h(acc2q[ntl][r]), blo);
                __half2 ph = __hadd2(u2h(acc2q[ntl + 2][r]), bhi);
                __half2 ylo = __hsub2(__hmul2(pl, u2h(cl.x)), __hmul2(ph, u2h(cl.y)));
                __half2 yhi = __hfma2(pl, u2h(ch.y), __hmul2(ph, u2h(ch.x)));
                aq0[2 * ntl + r] = h2u(__hmul2(ylo, sc2));
                aq1[2 * ntl + r] = h2u(__hmul2(yhi, sc2));
            }
        }

        // S = Q K^T over 96 keys (fp16 accumulators)
        unsigned sacc2[12][2] = {};
        #pragma unroll
        for (int p = 0; p < 6; p++) {
            unsigned b[4];
            ldsm4(b, kb0[p]);
            mma16816hh(sacc2[2 * p], aq0, &b[0]);
            mma16816hh(sacc2[2 * p + 1], aq0, &b[2]);
        }
        #pragma unroll
        for (int p = 0; p < 6; p++) {
            unsigned b[4];
            ldsm4(b, kb0[p] ^ 32u);
            mma16816hh(sacc2[2 * p], aq1, &b[0]);
            mma16816hh(sacc2[2 * p + 1], aq1, &b[2]);
        }

        // fp16x2 softmax; normalized P accumulated into hxa/hya via HFMA2 (1/6 folded)
        unsigned hx[12], hy[12];
        #pragma unroll
        for (int nt = 0; nt < 12; nt++) {
            hx[nt] = ex2h2(sacc2[nt][0]);
            hy[nt] = ex2h2(sacc2[nt][1]);
        }
        __half2 s2x = u2h(hx[0]), s2y = u2h(hy[0]);
        #pragma unroll
        for (int nt = 1; nt < 12; nt++) {
            s2x = __hadd2(s2x, u2h(hx[nt]));
            s2y = __hadd2(s2y, u2h(hy[nt]));
        }
        float sm0 = __low2float(s2x) + __high2float(s2x);
        float sm1 = __low2float(s2y) + __high2float(s2y);
        sm0 += __shfl_xor_sync(0xffffffffu, sm0, 1);
        sm0 += __shfl_xor_sync(0xffffffffu, sm0, 2);
        sm1 += __shfl_xor_sync(0xffffffffu, sm1, 1);
        sm1 += __shfl_xor_sync(0xffffffffu, sm1, 2);
        float r0i = __fdividef(0.16666667f, sm0);
        float r1i = __fdividef(0.16666667f, sm1);
        __half2 h2r0 = u2h(cvth2(r0i, r0i));
        __half2 h2r1 = u2h(cvth2(r1i, r1i));
        #pragma unroll
        for (int nt = 0; nt < 12; nt++) {
            hxa[nt] = h2u(__hfma2(u2h(hx[nt]), h2r0, u2h(hxa[nt])));
            hya[nt] = h2u(__hfma2(u2h(hy[nt]), h2r1, u2h(hya[nt])));
        }

        if (j == 5) {
            // single PV over view-summed P-hat for even uv-half -> g_tmp
            float ofl[4][4] = {};
            #pragma unroll
            for (int c6 = 0; c6 < 6; c6++) {
                unsigned a[4];
                a[0] = hxa[2 * c6];
                a[1] = hya[2 * c6];
                a[2] = hxa[2 * c6 + 1];
                a[3] = hya[2 * c6 + 1];
                #pragma unroll
                for (int p = 0; p < 2; p++) {
                    unsigned b[4];
                    ldsm4(b, vb[p] + c6 * 32);
                    mma16816h(ofl[2 * p], a, &b[0]);
                    mma16816h(ofl[2 * p + 1], a, &b[2]);
                }
            }
            #pragma unroll
            for (int nt = 0; nt < 4; nt++) {
                int col = mh * 32 + nt * 8 + 2 * t4;
                #pragma unroll
                for (int r = 0; r < 2; r++) {
                    int uv = mrow + gq + 8 * r;
                    *reinterpret_cast<unsigned*>(g_tmp + (size_t)l * 4096 + uv * 128 + col) =
                        pk(ofl[nt][2 * r], ofl[nt][2 * r + 1]);
                }
            }
            #pragma unroll
            for (int nt = 0; nt < 12; nt++) { hxa[nt] = 0u; hya[nt] = 0u; }
        } else if (j == 11) {
            // single PV for odd uv-half -> oacc (kept in registers for Phase C)
            #pragma unroll
            for (int c6 = 0; c6 < 6; c6++) {
                unsigned a[4];
                a[0] = hxa[2 * c6];
                a[1] = hya[2 * c6];
                a[2] = hxa[2 * c6 + 1];
                a[3] = hya[2 * c6 + 1];
                #pragma unroll
                for (int p = 0; p < 2; p++) {
                    unsigned b[4];
                    ldsm4(b, vb[p] + c6 * 32);
                    mma16816h(oacc[2 * p], a, &b[0]);
                    mma16816h(oacc[2 * p + 1], a, &b[2]);
                }
            }
        }
    }

    // =========================== Phase C: mean -> proj -> +skip -> out ===========================
    __syncthreads();   // all attention reads of sK/sVt/sW/raw done

    // odd uv-half: registers -> rawO rows 32..63 (swizzled bf16 64x128)
    #pragma unroll
    for (int nt = 0; nt < 4; nt++) {
        int col = mh * 32 + nt * 8 + 2 * t4;
        int cu = col >> 3;
        #pragma unroll
        for (int r = 0; r < 2; r++) {
            int row = 32 + mrow + gq + 8 * r;
            *reinterpret_cast<unsigned*>(&rawO[row * 128 + ((cu ^ (row & 7)) << 3) + (col & 7)]) =
                pk(oacc[nt][2 * r], oacc[nt][2 * r + 1]);
        }
    }
    // stage wp, even uv-half (g_tmp), skip
    stage_w(sW, g_wp, tid);
    #pragma unroll
    for (int u = tid; u < 512; u += 256) {
        int row = u >> 4, cu = u & 15;
        cpa16(&rawO[row * 128 + ((cu ^ (row & 7)) << 3)],
              g_tmp + (size_t)l * 4096 + row * 128 + cu * 8);
    }
    float* sSkip = reinterpret_cast<float*>(sm + E_K);   // 32 KB inside dead sK/sVt region
    #pragma unroll
    for (int u = tid; u < 2048; u += 256)
        cpa16(sSkip + u * 4, skip + (size_t)l * 8192 + u * 4);
    cpa_commit();
    cpa_wait<0>();
    __syncthreads();

    // proj GEMM: 64 rows x 128 cols
    {
        int rh = wid & 3, cg = wid >> 2;
        int prowA = rh * 16 + (lane & 15);
        unsigned paRow = ssa(rawO) + prowA * 256;
        int parx = prowA & 7, pau0 = lane >> 4;
        int op = cg * 64 + ((lane >> 4) << 3) + (lane & 7);
        unsigned pw0 = sWb + op * 256;
        int prx = op & 7;
        float pacc[8][4] = {};
        #pragma unroll
        for (int kk = 0; kk < 128; kk += 16) {
            unsigned a[4];
            ldsm4(a, paRow + ((((kk >> 3) + pau0) ^ parx) << 4));
            unsigned uoff = ((((kk >> 3) + wu0) ^ prx) << 4);
            #pragma unroll
            for (int p = 0; p < 4; p++) {
                unsigned b[4];
                ldsm4(b, pw0 + p * 4096 + uoff);
                mma16816(pacc[2 * p], a, &b[0]);
                mma16816(pacc[2 * p + 1], a, &b[2]);
            }
        }
        #pragma unroll
        for (int nt = 0; nt < 8; nt++) {
            int col = cg * 64 + nt * 8 + 2 * t4;
            float2 bp = *reinterpret_cast<const float2*>(&bproj[col]);
            #pragma unroll
            for (int r = 0; r < 2; r++) {
                int rloc = rh * 16 + gq + 8 * r;
                float2 sk = *reinterpret_cast<const float2*>(sSkip + rloc * 128 + col);
                float2 o2;
                o2.x = pacc[nt][2 * r] + bp.x + sk.x;
                o2.y = pacc[nt][2 * r + 1] + bp.y + sk.y;
                *reinterpret_cast<float2*>(out + ((size_t)l * 64 + rloc) * 128 + col) = o2;
            }
        }
    }
}

// ---------------- launch ----------------
extern "C" void kernel_launch(void* const* d_in, const int* in_sizes, int n_in,
                              void* d_out, int out_size) {
    const float* q     = (const float*)d_in[0];
    const float* k     = (const float*)d_in[1];
    const float* v     = (const float*)d_in[2];
    const float* skip  = (const float*)d_in[3];
    const float* freqs = (const float*)d_in[4];
    const float* gate  = (const float*)d_in[5];
    const float* lnqg  = (const float*)d_in[6];
    const float* lnqb  = (const float*)d_in[7];
    const float* lnkg  = (const float*)d_in[8];
    const float* lnkb  = (const float*)d_in[9];
    const float* lnvg  = (const float*)d_in[10];
    const float* lnvb  = (const float*)d_in[11];
    const float* wq    = (const float*)d_in[12];
    const float* bq    = (const float*)d_in[13];
    const float* wk    = (const float*)d_in[14];
    const float* bk    = (const float*)d_in[15];
    const float* wv    = (const float*)d_in[16];
    const float* bv    = (const float*)d_in[17];
    const float* wproj = (const float*)d_in[18];
    const float* bproj = (const float*)d_in[19];
    const float* als   = (const float*)d_in[20];
    float* out = (float*)d_out;

    static int smem_set = 0;
    if (!smem_set) {
        cudaFuncSetAttribute(fused_kernel, cudaFuncAttributeMaxDynamicSharedMemorySize, SMEM_BYTES);
        smem_set = 1;
    }

    prep_const_kernel<<<329, 256>>>(wq, wk, wv, wproj, freqs, gate, als, bq);
    fused_kernel<<<LTOT, 256, SMEM_BYTES>>>(q, k, v, skip,
                                            lnqg, lnqb, lnkg, lnkb, lnvg, lnvb,
                                            bk, bv, bproj, out);
}